// round 9
// baseline (speedup 1.0000x reference)
#include <cuda_runtime.h>
#include <math.h>

// ---------------------------------------------------------------------------
// Problem constants
// ---------------------------------------------------------------------------
#define NTOK   1024
#define BATCH  8
#define DIN    256
#define HIDW   256
#define NROWS  (NTOK * BATCH)      // 8192
#define NHEAD  8
#define DH     32
#define SH_    2
#define LH_    4
#define LEPS   1e-5f

// ---------------------------------------------------------------------------
// Scratch (static device globals — no allocation allowed)
// ---------------------------------------------------------------------------
__device__ float g_a  [NROWS * DIN];        // nodes + PE
__device__ float g_x  [NROWS * HIDW];       // running activations
__device__ float g_y  [NROWS * HIDW];       // pre-LN GEMM outputs
__device__ float g_qkv[NROWS * 3 * HIDW];   // qkv (also reused for FFN hidden 8192x512)
__device__ float g_o  [NROWS * HIDW];       // attention output
__device__ float g_den[DIN];                // PE denominators

// ---------------------------------------------------------------------------
// PE denominator table: den[k] = 10000 ^ (2*floor(k/2)/256), fp32-rounded
// ---------------------------------------------------------------------------
__global__ void pe_table_kernel(float* den) {
    int k = threadIdx.x;
    float e = (float)(2 * (k >> 1)) / 256.0f;       // exact in fp32
    den[k] = (float)pow(10000.0, (double)e);
}

// x = nodes + PE  (layout (N,B,DIN) row-major == linear idx)
__global__ __launch_bounds__(256) void add_pe_kernel(
    const float* __restrict__ nodes, const float* __restrict__ den,
    float* __restrict__ out)
{
    int idx = blockIdx.x * 256 + threadIdx.x;       // 0 .. 2M-1
    int n = idx >> 11;                              // B*DIN = 2048
    int k = idx & 255;
    float ang = (float)n / den[k];
    double sv = (k & 1) ? cos((double)ang) : sin((double)ang);
    out[idx] = nodes[idx] + (float)sv;
}

// ---------------------------------------------------------------------------
// Tiled SGEMM:  C[M,Nc] = A[M,K] @ B[K,Nc] + bias[Nc]   (optional ReLU)
// BM=128, BN=64, BK=16, 256 threads, 8x4 register tile.
// Requires M%128==0, Nc%64==0, K%16==0 (always true here).
// ---------------------------------------------------------------------------
#define GBM 128
#define GBN 64
#define GBK 16

__global__ __launch_bounds__(256) void sgemm_bias_kernel(
    const float* __restrict__ A, const float* __restrict__ B,
    const float* __restrict__ bias, float* __restrict__ C,
    int M, int Nc, int K, int relu)
{
    __shared__ float As[GBK][GBM + 4];   // stride 132 floats (528B, 16B-aligned)
    __shared__ float Bs[GBK][GBN + 4];   // stride  68 floats (272B, 16B-aligned)

    const int tid = threadIdx.x;
    const int ty = tid >> 4;             // 0..15 -> rows
    const int tx = tid & 15;             // 0..15 -> cols
    const int mBase = blockIdx.y * GBM;
    const int nBase = blockIdx.x * GBN;

    float acc[8][4];
#pragma unroll
    for (int i = 0; i < 8; i++)
#pragma unroll
        for (int j = 0; j < 4; j++) acc[i][j] = 0.0f;

    const int aRow0 = tid >> 2;          // + 64 on second pass
    const int aCol0 = (tid & 3) * 4;
    const int bK = tid >> 4;
    const int bC = (tid & 15) * 4;

    for (int kb = 0; kb < K; kb += GBK) {
        // A tile (128x16) -> transposed As[k][m]
#pragma unroll
        for (int it = 0; it < 2; it++) {
            int r = aRow0 + it * 64;
            float4 v = *(const float4*)(A + (size_t)(mBase + r) * K + kb + aCol0);
            As[aCol0 + 0][r] = v.x;
            As[aCol0 + 1][r] = v.y;
            As[aCol0 + 2][r] = v.z;
            As[aCol0 + 3][r] = v.w;
        }
        // B tile (16x64) row-major
        {
            float4 v = *(const float4*)(B + (size_t)(kb + bK) * Nc + nBase + bC);
            *(float4*)&Bs[bK][bC] = v;
        }
        __syncthreads();

#pragma unroll
        for (int k = 0; k < GBK; k++) {
            float4 a0 = *(const float4*)&As[k][ty * 8];
            float4 a1 = *(const float4*)&As[k][ty * 8 + 4];
            float4 b0 = *(const float4*)&Bs[k][tx * 4];
            float av[8] = {a0.x, a0.y, a0.z, a0.w, a1.x, a1.y, a1.z, a1.w};
            float bv[4] = {b0.x, b0.y, b0.z, b0.w};
#pragma unroll
            for (int i = 0; i < 8; i++)
#pragma unroll
                for (int j = 0; j < 4; j++) acc[i][j] += av[i] * bv[j];
        }
        __syncthreads();
    }

    // Epilogue: bias (+ReLU), vectorized store
    float4 bb = *(const float4*)(bias + nBase + tx * 4);
    float bv[4] = {bb.x, bb.y, bb.z, bb.w};
#pragma unroll
    for (int i = 0; i < 8; i++) {
        float4 v;
        float t0 = acc[i][0] + bv[0];
        float t1 = acc[i][1] + bv[1];
        float t2 = acc[i][2] + bv[2];
        float t3 = acc[i][3] + bv[3];
        if (relu) {
            t0 = fmaxf(t0, 0.0f); t1 = fmaxf(t1, 0.0f);
            t2 = fmaxf(t2, 0.0f); t3 = fmaxf(t3, 0.0f);
        }
        v.x = t0; v.y = t1; v.z = t2; v.w = t3;
        *(float4*)(C + (size_t)(mBase + ty * 8 + i) * Nc + nBase + tx * 4) = v;
    }
}

// ---------------------------------------------------------------------------
// LayerNorm over HID=256 per row; optional residual: out = LN(y + res)
// One block (256 threads) per row. In-place (out==res) is safe.
// ---------------------------------------------------------------------------
__global__ __launch_bounds__(256) void ln_kernel(
    const float* __restrict__ y, const float* __restrict__ res,
    const float* __restrict__ g, const float* __restrict__ bt,
    float* __restrict__ out)
{
    __shared__ float red[8];
    const int r = blockIdx.x;
    const int c = threadIdx.x;

    float v = y[(size_t)r * HIDW + c];
    if (res) v += res[(size_t)r * HIDW + c];

    float s = v;
#pragma unroll
    for (int off = 16; off; off >>= 1) s += __shfl_xor_sync(0xffffffffu, s, off);
    if ((c & 31) == 0) red[c >> 5] = s;
    __syncthreads();
    float tot = 0.0f;
#pragma unroll
    for (int i = 0; i < 8; i++) tot += red[i];
    float mu = tot * (1.0f / HIDW);

    float d = v - mu;
    float s2 = d * d;
#pragma unroll
    for (int off = 16; off; off >>= 1) s2 += __shfl_xor_sync(0xffffffffu, s2, off);
    __syncthreads();
    if ((c & 31) == 0) red[c >> 5] = s2;
    __syncthreads();
    float tv = 0.0f;
#pragma unroll
    for (int i = 0; i < 8; i++) tv += red[i];
    float var = tv * (1.0f / HIDW);

    out[(size_t)r * HIDW + c] = d * rsqrtf(var + LEPS) * g[c] + bt[c];
}

// ---------------------------------------------------------------------------
// Flash attention.  grid = (N/64 q-tiles, B*H).  256 threads.
// qkv layout: [(n*B+b)*768 + {0,256,512} + h*32 + d]
// out layout: [(n*B+b)*256 + h*32 + d]
// mask: h<2 -> dist==1 ; h<6 -> dist>=1 ; else none
// ---------------------------------------------------------------------------
#define QT 64
#define KT 64

__global__ __launch_bounds__(256) void flash_attn_kernel(
    const float* __restrict__ qkv, const int* __restrict__ dist,
    float* __restrict__ out)
{
    __shared__ float qs[DH][QT + 4];    // transposed, stride 68
    __shared__ float ks[DH][KT + 4];    // transposed, stride 68
    __shared__ float vs[KT][36];        // row-major, stride 36 (16B-aligned)
    __shared__ float ps[QT][KT + 4];    // probabilities, stride 68
    __shared__ float m_row[QT], l_row[QT], a_row[QT];

    const int tid = threadIdx.x;
    const int bh = blockIdx.y;
    const int b = bh >> 3;
    const int h = bh & 7;
    const int qbase = blockIdx.x * QT;
    const int mtype = (h < SH_) ? 1 : (h < SH_ + LH_) ? 2 : 0;
    const float SCALE = 0.17677669529663687f;   // 1/sqrt(32)

    // ---- load Q tile transposed (once) ----
#pragma unroll
    for (int it = 0; it < 2; it++) {
        int f = tid + it * 256;
        int row = f >> 3;
        int d = (f & 7) * 4;
        float4 v = *(const float4*)(qkv + ((size_t)(qbase + row) * BATCH + b) * 768 + h * 32 + d);
        qs[d + 0][row] = v.x; qs[d + 1][row] = v.y;
        qs[d + 2][row] = v.z; qs[d + 3][row] = v.w;
    }
    if (tid < QT) { m_row[tid] = -1e30f; l_row[tid] = 0.0f; }

    float oacc[4][2];
#pragma unroll
    for (int i = 0; i < 4; i++) { oacc[i][0] = 0.0f; oacc[i][1] = 0.0f; }

    const int ty = tid >> 4;     // score-phase row group (4 rows)
    const int tx = tid & 15;     // score-phase col group (4 cols)

    for (int kt = 0; kt < NTOK / KT; kt++) {
        const int kb = kt * KT;
        __syncthreads();   // prior O-phase done reading ks/vs/ps

        // ---- load K (transposed) and V (row-major) tiles ----
#pragma unroll
        for (int it = 0; it < 2; it++) {
            int f = tid + it * 256;
            int row = f >> 3;
            int d = (f & 7) * 4;
            size_t base = ((size_t)(kb + row) * BATCH + b) * 768 + h * 32 + d;
            float4 kv = *(const float4*)(qkv + base + 256);
            ks[d + 0][row] = kv.x; ks[d + 1][row] = kv.y;
            ks[d + 2][row] = kv.z; ks[d + 3][row] = kv.w;
            float4 vv = *(const float4*)(qkv + base + 512);
            *(float4*)&vs[row][d] = vv;
        }
        __syncthreads();

        // ---- score phase: 4x4 register tile ----
        float acc[4][4];
#pragma unroll
        for (int i = 0; i < 4; i++)
#pragma unroll
            for (int j = 0; j < 4; j++) acc[i][j] = 0.0f;

#pragma unroll
        for (int d = 0; d < DH; d++) {
            float4 aq = *(const float4*)&qs[d][ty * 4];
            float4 bk = *(const float4*)&ks[d][tx * 4];
            float av[4] = {aq.x, aq.y, aq.z, aq.w};
            float bv[4] = {bk.x, bk.y, bk.z, bk.w};
#pragma unroll
            for (int i = 0; i < 4; i++)
#pragma unroll
                for (int j = 0; j < 4; j++) acc[i][j] += av[i] * bv[j];
        }

        float sv[4][4];
        if (mtype) {
#pragma unroll
            for (int i = 0; i < 4; i++) {
                const int4 dd = *(const int4*)(dist + (size_t)b * NTOK * NTOK
                                               + (size_t)(qbase + ty * 4 + i) * NTOK + kb + tx * 4);
                int dv[4] = {dd.x, dd.y, dd.z, dd.w};
#pragma unroll
                for (int j = 0; j < 4; j++) {
                    bool ok = (mtype == 1) ? (dv[j] == 1) : (dv[j] >= 1);
                    sv[i][j] = acc[i][j] * SCALE + (ok ? 0.0f : -1e30f);
                }
            }
        } else {
#pragma unroll
            for (int i = 0; i < 4; i++)
#pragma unroll
                for (int j = 0; j < 4; j++) sv[i][j] = acc[i][j] * SCALE;
        }

        // row max across 16 lanes (tile-local)
        float mloc[4];
#pragma unroll
        for (int i = 0; i < 4; i++)
            mloc[i] = fmaxf(fmaxf(sv[i][0], sv[i][1]), fmaxf(sv[i][2], sv[i][3]));
#pragma unroll
        for (int off = 8; off; off >>= 1)
#pragma unroll
            for (int i = 0; i < 4; i++)
                mloc[i] = fmaxf(mloc[i], __shfl_xor_sync(0xffffffffu, mloc[i], off));

        float mnew[4], alpha[4];
#pragma unroll
        for (int i = 0; i < 4; i++) {
            float mp = m_row[ty * 4 + i];
            mnew[i] = fmaxf(mp, mloc[i]);
            alpha[i] = __expf(mp - mnew[i]);
        }

        float pv[4][4], rsum[4];
#pragma unroll
        for (int i = 0; i < 4; i++) {
#pragma unroll
            for (int j = 0; j < 4; j++) {
                float s = sv[i][j];
                pv[i][j] = (s < -1e29f) ? 0.0f : __expf(s - mnew[i]);
            }
            rsum[i] = (pv[i][0] + pv[i][1]) + (pv[i][2] + pv[i][3]);
        }
#pragma unroll
        for (int off = 8; off; off >>= 1)
#pragma unroll
            for (int i = 0; i < 4; i++)
                rsum[i] += __shfl_xor_sync(0xffffffffu, rsum[i], off);

#pragma unroll
        for (int i = 0; i < 4; i++) {
            float4 pw = make_float4(pv[i][0], pv[i][1], pv[i][2], pv[i][3]);
            *(float4*)&ps[ty * 4 + i][tx * 4] = pw;
        }
        if (tx == 0) {
#pragma unroll
            for (int i = 0; i < 4; i++) {
                int r = ty * 4 + i;
                m_row[r] = mnew[i];
                l_row[r] = l_row[r] * alpha[i] + rsum[i];
                a_row[r] = alpha[i];
            }
        }
        __syncthreads();

        // ---- O accumulation phase: 4 rows x 2 d per thread ----
        {
            const int r0 = (tid >> 4) * 4;
            const int d0 = (tid & 15) * 2;
            float al[4];
#pragma unroll
            for (int i = 0; i < 4; i++) {
                al[i] = a_row[r0 + i];
                oacc[i][0] *= al[i];
                oacc[i][1] *= al[i];
            }
#pragma unroll 4
            for (int c = 0; c < KT; c++) {
                float2 v = *(const float2*)&vs[c][d0];
#pragma unroll
                for (int i = 0; i < 4; i++) {
                    float p = ps[r0 + i][c];
                    oacc[i][0] += p * v.x;
                    oacc[i][1] += p * v.y;
                }
            }
        }
    }

    // ---- write out ----
    {
        const int r0 = (tid >> 4) * 4;
        const int d0 = (tid & 15) * 2;
#pragma unroll
        for (int i = 0; i < 4; i++) {
            int r = r0 + i;
            float inv = 1.0f / l_row[r];
            float2 o2 = make_float2(oacc[i][0] * inv, oacc[i][1] * inv);
            *(float2*)(out + ((size_t)(qbase + r) * BATCH + b) * HIDW + h * 32 + d0) = o2;
        }
    }
}

// ---------------------------------------------------------------------------
// Final batch-norm over B=8 at position n=0:  out[b,c]
// ---------------------------------------------------------------------------
__global__ __launch_bounds__(256) void bn_final_kernel(
    const float* __restrict__ x, const float* __restrict__ g,
    const float* __restrict__ bt, float* __restrict__ out)
{
    int c = threadIdx.x;
    float v[BATCH];
    float mu = 0.0f;
#pragma unroll
    for (int b = 0; b < BATCH; b++) {
        v[b] = x[(size_t)b * HIDW + c];   // rows of x at n=0 are b=0..7
        mu += v[b];
    }
    mu *= (1.0f / BATCH);
    float var = 0.0f;
#pragma unroll
    for (int b = 0; b < BATCH; b++) {
        float d = v[b] - mu;
        var += d * d;
    }
    var *= (1.0f / BATCH);
    float rs = rsqrtf(var + LEPS);
#pragma unroll
    for (int b = 0; b < BATCH; b++)
        out[b * HIDW + c] = (v[b] - mu) * rs * g[c] + bt[c];
}

// ---------------------------------------------------------------------------
// Launch
// ---------------------------------------------------------------------------
extern "C" void kernel_launch(void* const* d_in, const int* in_sizes, int n_in,
                              void* d_out, int out_size)
{
    const float* nodes   = (const float*)d_in[0];
    const int*   dist    = (const int*)  d_in[1];
    const float* W_in    = (const float*)d_in[2];
    const float* b_in    = (const float*)d_in[3];
    const float* ln_in_g = (const float*)d_in[4];
    const float* ln_in_b = (const float*)d_in[5];
    const float* Wqkv    = (const float*)d_in[6];
    const float* bqkv    = (const float*)d_in[7];
    const float* Wo      = (const float*)d_in[8];
    const float* bo      = (const float*)d_in[9];
    const float* ln1_g   = (const float*)d_in[10];
    const float* ln1_b   = (const float*)d_in[11];
    const float* W1      = (const float*)d_in[12];
    const float* b1      = (const float*)d_in[13];
    const float* W2      = (const float*)d_in[14];
    const float* b2      = (const float*)d_in[15];
    const float* ln2_g   = (const float*)d_in[16];
    const float* ln2_b   = (const float*)d_in[17];
    const float* bn_g    = (const float*)d_in[18];
    const float* bn_b    = (const float*)d_in[19];
    float* outp = (float*)d_out;

    float *a, *x, *y, *qkv, *o, *den;
    cudaGetSymbolAddress((void**)&a,   g_a);
    cudaGetSymbolAddress((void**)&x,   g_x);
    cudaGetSymbolAddress((void**)&y,   g_y);
    cudaGetSymbolAddress((void**)&qkv, g_qkv);
    cudaGetSymbolAddress((void**)&o,   g_o);
    cudaGetSymbolAddress((void**)&den, g_den);

    // 1. PE table + embed
    pe_table_kernel<<<1, 256>>>(den);
    add_pe_kernel<<<(NROWS * DIN) / 256, 256>>>(nodes, den, a);

    // 2. input projection + LN
    sgemm_bias_kernel<<<dim3(256 / GBN, NROWS / GBM), 256>>>(a, W_in, b_in, y,
                                                             NROWS, 256, 256, 0);
    ln_kernel<<<NROWS, 256>>>(y, nullptr, ln_in_g, ln_in_b, x);

    // 3. transformer layers
    for (int l = 0; l < 2; l++) {
        sgemm_bias_kernel<<<dim3(768 / GBN, NROWS / GBM), 256>>>(
            x, Wqkv + (size_t)l * 256 * 768, bqkv + l * 768, qkv,
            NROWS, 768, 256, 0);

        flash_attn_kernel<<<dim3(NTOK / QT, BATCH * NHEAD), 256>>>(qkv, dist, o);

        sgemm_bias_kernel<<<dim3(256 / GBN, NROWS / GBM), 256>>>(
            o, Wo + (size_t)l * 256 * 256, bo + l * 256, y,
            NROWS, 256, 256, 0);
        ln_kernel<<<NROWS, 256>>>(y, x, ln1_g + l * 256, ln1_b + l * 256, x);

        sgemm_bias_kernel<<<dim3(512 / GBN, NROWS / GBM), 256>>>(
            x, W1 + (size_t)l * 256 * 512, b1 + l * 512, qkv,
            NROWS, 512, 256, 1 /*relu*/);
        sgemm_bias_kernel<<<dim3(256 / GBN, NROWS / GBM), 256>>>(
            qkv, W2 + (size_t)l * 512 * 256, b2 + l * 256, y,
            NROWS, 256, 512, 0);
        ln_kernel<<<NROWS, 256>>>(y, x, ln2_g + l * 256, ln2_b + l * 256, x);
    }

    // 4. final batch-norm of x[0]
    bn_final_kernel<<<1, 256>>>(x, bn_g, bn_b, outp);
}

// round 13
// speedup vs baseline: 1.1360x; 1.1360x over previous
#include <cuda_runtime.h>
#include <cuda_bf16.h>
#include <math.h>

// ---------------------------------------------------------------------------
// Problem constants
// ---------------------------------------------------------------------------
#define NTOK   1024
#define BATCH  8
#define DIN    256
#define HIDW   256
#define NROWS  (NTOK * BATCH)      // 8192
#define NHEAD  8
#define DH     32
#define SH_    2
#define LH_    4
#define LEPS   1e-5f

// ---------------------------------------------------------------------------
// Scratch (static device globals — no allocation allowed)
// ---------------------------------------------------------------------------
__device__ __align__(16) float g_a  [NROWS * DIN];
__device__ __align__(16) float g_x  [NROWS * HIDW];
__device__ __align__(16) float g_y  [NROWS * HIDW];
__device__ __align__(16) float g_qkv[NROWS * 3 * HIDW];
__device__ __align__(16) float g_o  [NROWS * HIDW];
__device__ float g_den[DIN];
__device__ __align__(16) __nv_bfloat16 g_abf[NROWS * 1024];  // A hi|lo (max 2K=1024)
__device__ __align__(16) __nv_bfloat16 g_wt [768 * 1024];    // W^T hi|lo

// ---------------------------------------------------------------------------
// Split-precision conversion kernels (fp32 -> bf16 hi|lo)
// ---------------------------------------------------------------------------
__global__ __launch_bounds__(256) void convA_kernel(
    const float* __restrict__ s, __nv_bfloat16* __restrict__ d, int kshift)
{
    int idx = blockIdx.x * 256 + threadIdx.x;
    int K = 1 << kshift;
    int m = idx >> kshift, k = idx & (K - 1);
    float w = s[idx];
    __nv_bfloat16 hi = __float2bfloat16(w);
    float lo = w - __bfloat162float(hi);
    __nv_bfloat16* row = d + ((size_t)m << (kshift + 1));
    row[k] = hi;
    row[K + k] = __float2bfloat16(lo);
}

// W [K, Nc] row-major -> Wt [Nc, 2K] bf16 (hi cols [0,K), lo cols [K,2K))
__global__ __launch_bounds__(256) void convW_kernel(
    const float* __restrict__ s, __nv_bfloat16* __restrict__ d, int K, int Nc)
{
    int idx = blockIdx.x * 256 + threadIdx.x;
    int k = idx / Nc, n = idx - k * Nc;
    float w = s[idx];
    __nv_bfloat16 hi = __float2bfloat16(w);
    float lo = w - __bfloat162float(hi);
    d[(size_t)n * 2 * K + k] = hi;
    d[(size_t)n * 2 * K + K + k] = __float2bfloat16(lo);
}

// ---------------------------------------------------------------------------
// HMMA bf16 GEMM:  C[M,Nc] = A'[M,3K] * W'[3K,Nc] + bias   (virtual K' = 3K)
// A2 physical [M,2K] = [Ah|Al]; Wt physical [Nc,2K] = [Wh^T|Wl^T].
// Virtual segments: s0 Ah*Wh, s1 Al*Wh, s2 Ah*Wl (Al*Wl dropped, ~1e-5 rel).
// CTA tile 128x128, BK=64, 256 threads = 8 warps (4M x 2N), warp tile 32x64.
// mma.sync.aligned.m16n8k16 bf16, fp32 accum. ldmatrix.x4 fragment loads.
// smem: 128B rows, 16B-chunk XOR swizzle (chunk ^ (row&7)) -> conflict-free.
// ---------------------------------------------------------------------------
__device__ __forceinline__ unsigned smem_u32(const void* p) {
    unsigned a;
    asm("{ .reg .u64 t; cvta.to.shared.u64 t, %1; cvt.u32.u64 %0, t; }"
        : "=r"(a) : "l"(p));
    return a;
}

#define LDSM_X4(r0, r1, r2, r3, addr) \
    asm volatile("ldmatrix.sync.aligned.m8n8.x4.shared.b16 {%0,%1,%2,%3}, [%4];" \
                 : "=r"(r0), "=r"(r1), "=r"(r2), "=r"(r3) : "r"(addr))

#define MMA16816(d, a, b0v, b1v) \
    asm volatile("mma.sync.aligned.m16n8k16.row.col.f32.bf16.bf16.f32 " \
                 "{%0,%1,%2,%3}, {%4,%5,%6,%7}, {%8,%9}, {%0,%1,%2,%3};" \
                 : "+f"((d)[0]), "+f"((d)[1]), "+f"((d)[2]), "+f"((d)[3]) \
                 : "r"((a)[0]), "r"((a)[1]), "r"((a)[2]), "r"((a)[3]), \
                   "r"(b0v), "r"(b1v))

__global__ __launch_bounds__(256, 2) void hmma_gemm_kernel(
    const __nv_bfloat16* __restrict__ A2, const __nv_bfloat16* __restrict__ Wt,
    const float* __restrict__ bias, float* __restrict__ C,
    int K, int Nc, int relu)
{
    __shared__ __align__(16) char As[128 * 128];   // 128 rows x 64 bf16 (128B)
    __shared__ __align__(16) char Bs[128 * 128];

    const int tid = threadIdx.x;
    const int wid = tid >> 5;
    const int lane = tid & 31;
    const int warpM = wid & 3;          // 0..3 -> 32-row slices
    const int warpN = wid >> 2;         // 0..1 -> 64-col slices
    const int wm0 = warpM * 32;
    const int wn0 = warpN * 64;
    const int mBase = blockIdx.y * 128;
    const int nBase = blockIdx.x * 128;
    const int stride2K = 2 * K;
    const int T = (3 * K) / 64;

    const unsigned asb = smem_u32(As);
    const unsigned bsb = smem_u32(Bs);

    float acc[2][8][4];
#pragma unroll
    for (int am = 0; am < 2; am++)
#pragma unroll
        for (int bn = 0; bn < 8; bn++)
#pragma unroll
            for (int c = 0; c < 4; c++) acc[am][bn][c] = 0.0f;

    // --- precomputed per-thread fragment addresses (chunk part added in loop)
    // A ldmatrix.x4 for (am): rows m0 + lane%16, chunk base + lane/16
    const int a_row_in = lane & 15;
    const int a_blk = lane >> 4;
    // B ldmatrix.x4 for (bn2): rows n0 + (lane>>4)*8... mapping below:
    //   q = lane/8: mat q -> n_row = n0 + (q>>1)*8 + lane%8, chunk = kc + (q&1)
    const int b_q = lane >> 3;
    const int b_r = lane & 7;

    for (int t = 0; t < T; t++) {
        const int kc64 = t * 64;
        const int aoff = (kc64 < 2 * K) ? kc64 : kc64 - 2 * K;
        const int woff = (kc64 < K) ? kc64 : kc64 - K;

        // ---- global -> smem (swizzled). 1024 int4 per operand, 4/thread ----
#pragma unroll
        for (int i = 0; i < 4; i++) {
            int idx = i * 256 + tid;
            int row = idx >> 3, ch = idx & 7;
            int sw = row * 128 + ((ch ^ (row & 7)) << 4);
            int4 va = *(const int4*)(A2 + (size_t)(mBase + row) * stride2K + aoff + ch * 8);
            *(int4*)(As + sw) = va;
            int4 vb = *(const int4*)(Wt + (size_t)(nBase + row) * stride2K + woff + ch * 8);
            *(int4*)(Bs + sw) = vb;
        }
        __syncthreads();

#pragma unroll
        for (int ks = 0; ks < 4; ks++) {
            const int kc = ks * 2;   // 16B-chunk index of this k16 pair

            // A fragments: 2 x ldmatrix.x4 (m16 x k16 each)
            unsigned af[2][4];
#pragma unroll
            for (int am = 0; am < 2; am++) {
                int row = wm0 + am * 16 + a_row_in;
                unsigned addr = asb + row * 128 + (((kc + a_blk) ^ (row & 7)) << 4);
                LDSM_X4(af[am][0], af[am][1], af[am][2], af[am][3], addr);
            }
            // B fragments: 4 x ldmatrix.x4, each covers 2 n-atoms (16 n)
            unsigned bf[4][4];
#pragma unroll
            for (int bn2 = 0; bn2 < 4; bn2++) {
                int n_row = wn0 + bn2 * 16 + ((b_q >> 1) << 3) + b_r;
                unsigned addr = bsb + n_row * 128 + (((kc + (b_q & 1)) ^ (n_row & 7)) << 4);
                LDSM_X4(bf[bn2][0], bf[bn2][1], bf[bn2][2], bf[bn2][3], addr);
            }
            // 16 mma
#pragma unroll
            for (int am = 0; am < 2; am++)
#pragma unroll
                for (int bn2 = 0; bn2 < 4; bn2++) {
                    MMA16816(acc[am][bn2 * 2 + 0], af[am], bf[bn2][0], bf[bn2][1]);
                    MMA16816(acc[am][bn2 * 2 + 1], af[am], bf[bn2][2], bf[bn2][3]);
                }
        }
        __syncthreads();
    }

    // ---- epilogue: bias (+ReLU), float2 stores ----
    const int gr = lane >> 2;
    const int gc = (lane & 3) * 2;
#pragma unroll
    for (int am = 0; am < 2; am++) {
#pragma unroll
        for (int bn = 0; bn < 8; bn++) {
            int col = nBase + wn0 + bn * 8 + gc;
            float b0 = bias[col], b1 = bias[col + 1];
            int row0 = mBase + wm0 + am * 16 + gr;
            float2 v0 = make_float2(acc[am][bn][0] + b0, acc[am][bn][1] + b1);
            float2 v1 = make_float2(acc[am][bn][2] + b0, acc[am][bn][3] + b1);
            if (relu) {
                v0.x = fmaxf(v0.x, 0.0f); v0.y = fmaxf(v0.y, 0.0f);
                v1.x = fmaxf(v1.x, 0.0f); v1.y = fmaxf(v1.y, 0.0f);
            }
            *(float2*)(C + (size_t)row0 * Nc + col) = v0;
            *(float2*)(C + (size_t)(row0 + 8) * Nc + col) = v1;
        }
    }
}

// ---------------------------------------------------------------------------
// PE denominator table + embed
// ---------------------------------------------------------------------------
__global__ void pe_table_kernel(float* den) {
    int k = threadIdx.x;
    float e = (float)(2 * (k >> 1)) / 256.0f;
    den[k] = (float)pow(10000.0, (double)e);
}

__global__ __launch_bounds__(256) void add_pe_kernel(
    const float* __restrict__ nodes, const float* __restrict__ den,
    float* __restrict__ out)
{
    int idx = blockIdx.x * 256 + threadIdx.x;
    int n = idx >> 11;
    int k = idx & 255;
    float ang = (float)n / den[k];
    double sv = (k & 1) ? cos((double)ang) : sin((double)ang);
    out[idx] = nodes[idx] + (float)sv;
}

// ---------------------------------------------------------------------------
// LayerNorm over HID=256 per row; optional residual: out = LN(y + res)
// ---------------------------------------------------------------------------
__global__ __launch_bounds__(256) void ln_kernel(
    const float* __restrict__ y, const float* __restrict__ res,
    const float* __restrict__ g, const float* __restrict__ bt,
    float* __restrict__ out)
{
    __shared__ float red[8];
    const int r = blockIdx.x;
    const int c = threadIdx.x;

    float v = y[(size_t)r * HIDW + c];
    if (res) v += res[(size_t)r * HIDW + c];

    float s = v;
#pragma unroll
    for (int off = 16; off; off >>= 1) s += __shfl_xor_sync(0xffffffffu, s, off);
    if ((c & 31) == 0) red[c >> 5] = s;
    __syncthreads();
    float tot = 0.0f;
#pragma unroll
    for (int i = 0; i < 8; i++) tot += red[i];
    float mu = tot * (1.0f / HIDW);

    float d = v - mu;
    float s2 = d * d;
#pragma unroll
    for (int off = 16; off; off >>= 1) s2 += __shfl_xor_sync(0xffffffffu, s2, off);
    __syncthreads();
    if ((c & 31) == 0) red[c >> 5] = s2;
    __syncthreads();
    float tv = 0.0f;
#pragma unroll
    for (int i = 0; i < 8; i++) tv += red[i];
    float var = tv * (1.0f / HIDW);

    out[(size_t)r * HIDW + c] = d * rsqrtf(var + LEPS) * g[c] + bt[c];
}

// ---------------------------------------------------------------------------
// Flash attention (fp32) — unchanged from R9 (known-passing).
// ---------------------------------------------------------------------------
#define QT 64
#define KT 64

__global__ __launch_bounds__(256) void flash_attn_kernel(
    const float* __restrict__ qkv, const int* __restrict__ dist,
    float* __restrict__ out)
{
    __shared__ float qs[DH][QT + 4];
    __shared__ float ks[DH][KT + 4];
    __shared__ float vs[KT][36];
    __shared__ float ps[QT][KT + 4];
    __shared__ float m_row[QT], l_row[QT], a_row[QT];

    const int tid = threadIdx.x;
    const int bh = blockIdx.y;
    const int b = bh >> 3;
    const int h = bh & 7;
    const int qbase = blockIdx.x * QT;
    const int mtype = (h < SH_) ? 1 : (h < SH_ + LH_) ? 2 : 0;
    const float SCALE = 0.17677669529663687f;

#pragma unroll
    for (int it = 0; it < 2; it++) {
        int f = tid + it * 256;
        int row = f >> 3;
        int d = (f & 7) * 4;
        float4 v = *(const float4*)(qkv + ((size_t)(qbase + row) * BATCH + b) * 768 + h * 32 + d);
        qs[d + 0][row] = v.x; qs[d + 1][row] = v.y;
        qs[d + 2][row] = v.z; qs[d + 3][row] = v.w;
    }
    if (tid < QT) { m_row[tid] = -1e30f; l_row[tid] = 0.0f; }

    float oacc[4][2];
#pragma unroll
    for (int i = 0; i < 4; i++) { oacc[i][0] = 0.0f; oacc[i][1] = 0.0f; }

    const int ty = tid >> 4;
    const int tx = tid & 15;

    for (int kt = 0; kt < NTOK / KT; kt++) {
        const int kb = kt * KT;
        __syncthreads();

#pragma unroll
        for (int it = 0; it < 2; it++) {
            int f = tid + it * 256;
            int row = f >> 3;
            int d = (f & 7) * 4;
            size_t base = ((size_t)(kb + row) * BATCH + b) * 768 + h * 32 + d;
            float4 kv = *(const float4*)(qkv + base + 256);
            ks[d + 0][row] = kv.x; ks[d + 1][row] = kv.y;
            ks[d + 2][row] = kv.z; ks[d + 3][row] = kv.w;
            float4 vv = *(const float4*)(qkv + base + 512);
            *(float4*)&vs[row][d] = vv;
        }
        __syncthreads();

        float acc[4][4];
#pragma unroll
        for (int i = 0; i < 4; i++)
#pragma unroll
            for (int j = 0; j < 4; j++) acc[i][j] = 0.0f;

#pragma unroll
        for (int d = 0; d < DH; d++) {
            float4 aq = *(const float4*)&qs[d][ty * 4];
            float4 bk = *(const float4*)&ks[d][tx * 4];
            float av[4] = {aq.x, aq.y, aq.z, aq.w};
            float bv[4] = {bk.x, bk.y, bk.z, bk.w};
#pragma unroll
            for (int i = 0; i < 4; i++)
#pragma unroll
                for (int j = 0; j < 4; j++) acc[i][j] += av[i] * bv[j];
        }

        float sv[4][4];
        if (mtype) {
#pragma unroll
            for (int i = 0; i < 4; i++) {
                const int4 dd = *(const int4*)(dist + (size_t)b * NTOK * NTOK
                                               + (size_t)(qbase + ty * 4 + i) * NTOK + kb + tx * 4);
                int dv[4] = {dd.x, dd.y, dd.z, dd.w};
#pragma unroll
                for (int j = 0; j < 4; j++) {
                    bool ok = (mtype == 1) ? (dv[j] == 1) : (dv[j] >= 1);
                    sv[i][j] = acc[i][j] * SCALE + (ok ? 0.0f : -1e30f);
                }
            }
        } else {
#pragma unroll
            for (int i = 0; i < 4; i++)
#pragma unroll
                for (int j = 0; j < 4; j++) sv[i][j] = acc[i][j] * SCALE;
        }

        float mloc[4];
#pragma unroll
        for (int i = 0; i < 4; i++)
            mloc[i] = fmaxf(fmaxf(sv[i][0], sv[i][1]), fmaxf(sv[i][2], sv[i][3]));
#pragma unroll
        for (int off = 8; off; off >>= 1)
#pragma unroll
            for (int i = 0; i < 4; i++)
                mloc[i] = fmaxf(mloc[i], __shfl_xor_sync(0xffffffffu, mloc[i], off));

        float mnew[4], alpha[4];
#pragma unroll
        for (int i = 0; i < 4; i++) {
            float mp = m_row[ty * 4 + i];
            mnew[i] = fmaxf(mp, mloc[i]);
            alpha[i] = __expf(mp - mnew[i]);
        }

        float pv[4][4], rsum[4];
#pragma unroll
        for (int i = 0; i < 4; i++) {
#pragma unroll
            for (int j = 0; j < 4; j++) {
                float s = sv[i][j];
                pv[i][j] = (s < -1e29f) ? 0.0f : __expf(s - mnew[i]);
            }
            rsum[i] = (pv[i][0] + pv[i][1]) + (pv[i][2] + pv[i][3]);
        }
#pragma unroll
        for (int off = 8; off; off >>= 1)
#pragma unroll
            for (int i = 0; i < 4; i++)
                rsum[i] += __shfl_xor_sync(0xffffffffu, rsum[i], off);

#pragma unroll
        for (int i = 0; i < 4; i++) {
            float4 pw = make_float4(pv[i][0], pv[i][1], pv[i][2], pv[i][3]);
            *(float4*)&ps[ty * 4 + i][tx * 4] = pw;
        }
        if (tx == 0) {
#pragma unroll
            for (int i = 0; i < 4; i++) {
                int r = ty * 4 + i;
                m_row[r] = mnew[i];
                l_row[r] = l_row[r] * alpha[i] + rsum[i];
                a_row[r] = alpha[i];
            }
        }
        __syncthreads();

        {
            const int r0 = (tid >> 4) * 4;
            const int d0 = (tid & 15) * 2;
            float al[4];
#pragma unroll
            for (int i = 0; i < 4; i++) {
                al[i] = a_row[r0 + i];
                oacc[i][0] *= al[i];
                oacc[i][1] *= al[i];
            }
#pragma unroll 4
            for (int c = 0; c < KT; c++) {
                float2 v = *(const float2*)&vs[c][d0];
#pragma unroll
                for (int i = 0; i < 4; i++) {
                    float p = ps[r0 + i][c];
                    oacc[i][0] += p * v.x;
                    oacc[i][1] += p * v.y;
                }
            }
        }
    }

    {
        const int r0 = (tid >> 4) * 4;
        const int d0 = (tid & 15) * 2;
#pragma unroll
        for (int i = 0; i < 4; i++) {
            int r = r0 + i;
            float inv = 1.0f / l_row[r];
            float2 o2 = make_float2(oacc[i][0] * inv, oacc[i][1] * inv);
            *(float2*)(out + ((size_t)(qbase + r) * BATCH + b) * HIDW + h * 32 + d0) = o2;
        }
    }
}

// ---------------------------------------------------------------------------
// Final batch-norm over B=8 at position n=0
// ---------------------------------------------------------------------------
__global__ __launch_bounds__(256) void bn_final_kernel(
    const float* __restrict__ x, const float* __restrict__ g,
    const float* __restrict__ bt, float* __restrict__ out)
{
    int c = threadIdx.x;
    float v[BATCH];
    float mu = 0.0f;
#pragma unroll
    for (int b = 0; b < BATCH; b++) {
        v[b] = x[(size_t)b * HIDW + c];
        mu += v[b];
    }
    mu *= (1.0f / BATCH);
    float var = 0.0f;
#pragma unroll
    for (int b = 0; b < BATCH; b++) {
        float d = v[b] - mu;
        var += d * d;
    }
    var *= (1.0f / BATCH);
    float rs = rsqrtf(var + LEPS);
#pragma unroll
    for (int b = 0; b < BATCH; b++)
        out[b * HIDW + c] = (v[b] - mu) * rs * g[c] + bt[c];
}

// ---------------------------------------------------------------------------
// Host-side GEMM wrapper: convert A + W to split bf16, run HMMA GEMM
// ---------------------------------------------------------------------------
static void tc_gemm(const float* Afp32, const float* W, const float* bias,
                    float* C, int K, int Nc, int relu,
                    __nv_bfloat16* abf, __nv_bfloat16* wt)
{
    int kshift = (K == 256) ? 8 : 9;
    convA_kernel<<<(NROWS * K) / 256, 256>>>(Afp32, abf, kshift);
    convW_kernel<<<(K * Nc) / 256, 256>>>(W, wt, K, Nc);
    hmma_gemm_kernel<<<dim3(Nc / 128, NROWS / 128), 256>>>(
        abf, wt, bias, C, K, Nc, relu);
}

// ---------------------------------------------------------------------------
// Launch
// ---------------------------------------------------------------------------
extern "C" void kernel_launch(void* const* d_in, const int* in_sizes, int n_in,
                              void* d_out, int out_size)
{
    const float* nodes   = (const float*)d_in[0];
    const int*   dist    = (const int*)  d_in[1];
    const float* W_in    = (const float*)d_in[2];
    const float* b_in    = (const float*)d_in[3];
    const float* ln_in_g = (const float*)d_in[4];
    const float* ln_in_b = (const float*)d_in[5];
    const float* Wqkv    = (const float*)d_in[6];
    const float* bqkv    = (const float*)d_in[7];
    const float* Wo      = (const float*)d_in[8];
    const float* bo      = (const float*)d_in[9];
    const float* ln1_g   = (const float*)d_in[10];
    const float* ln1_b   = (const float*)d_in[11];
    const float* W1      = (const float*)d_in[12];
    const float* b1      = (const float*)d_in[13];
    const float* W2      = (const float*)d_in[14];
    const float* b2      = (const float*)d_in[15];
    const float* ln2_g   = (const float*)d_in[16];
    const float* ln2_b   = (const float*)d_in[17];
    const float* bn_g    = (const float*)d_in[18];
    const float* bn_b    = (const float*)d_in[19];
    float* outp = (float*)d_out;

    float *a, *x, *y, *qkv, *o, *den;
    __nv_bfloat16 *abf, *wt;
    cudaGetSymbolAddress((void**)&a,   g_a);
    cudaGetSymbolAddress((void**)&x,   g_x);
    cudaGetSymbolAddress((void**)&y,   g_y);
    cudaGetSymbolAddress((void**)&qkv, g_qkv);
    cudaGetSymbolAddress((void**)&o,   g_o);
    cudaGetSymbolAddress((void**)&den, g_den);
    cudaGetSymbolAddress((void**)&abf, g_abf);
    cudaGetSymbolAddress((void**)&wt,  g_wt);

    // 1. PE table + embed
    pe_table_kernel<<<1, 256>>>(den);
    add_pe_kernel<<<(NROWS * DIN) / 256, 256>>>(nodes, den, a);

    // 2. input projection + LN
    tc_gemm(a, W_in, b_in, y, 256, 256, 0, abf, wt);
    ln_kernel<<<NROWS, 256>>>(y, nullptr, ln_in_g, ln_in_b, x);

    // 3. transformer layers
    for (int l = 0; l < 2; l++) {
        tc_gemm(x, Wqkv + (size_t)l * 256 * 768, bqkv + l * 768, qkv,
                256, 768, 0, abf, wt);

        flash_attn_kernel<<<dim3(NTOK / QT, BATCH * NHEAD), 256>>>(qkv, dist, o);

        tc_gemm(o, Wo + (size_t)l * 256 * 256, bo + l * 256, y,
                256, 256, 0, abf, wt);
        ln_kernel<<<NROWS, 256>>>(y, x, ln1_g + l * 256, ln1_b + l * 256, x);

        tc_gemm(x, W1 + (size_t)l * 256 * 512, b1 + l * 512, qkv,
                256, 512, 1 /*relu*/, abf, wt);
        tc_gemm(qkv, W2 + (size_t)l * 512 * 256, b2 + l * 256, y,
                512, 256, 0, abf, wt);
        ln_kernel<<<NROWS, 256>>>(y, x, ln2_g + l * 256, ln2_b + l * 256, x);
    }

    // 4. final batch-norm of x[0]
    bn_final_kernel<<<1, 256>>>(x, bn_g, bn_b, outp);
}

// round 14
// speedup vs baseline: 1.5894x; 1.3990x over previous
#include <cuda_runtime.h>
#include <cuda_bf16.h>
#include <math.h>

// ---------------------------------------------------------------------------
// Problem constants
// ---------------------------------------------------------------------------
#define NTOK   1024
#define BATCH  8
#define DIN    256
#define HIDW   256
#define NROWS  (NTOK * BATCH)      // 8192
#define NHEAD  8
#define DH     32
#define LEPS   1e-5f

// ---------------------------------------------------------------------------
// Scratch (static device globals — no allocation allowed)
// ---------------------------------------------------------------------------
__device__ __align__(16) float g_a  [NROWS * DIN];
__device__ __align__(16) float g_x  [NROWS * HIDW];
__device__ __align__(16) float g_y  [NROWS * HIDW];
__device__ __align__(16) float g_qkv[NROWS * 3 * HIDW];   // qkv fp32 / FFN hidden
__device__ float g_den[DIN];
__device__ __align__(16) __nv_bfloat16 g_abf[NROWS * 1024];  // A hi|lo (max 2K=1024)
__device__ __align__(16) __nv_bfloat16 g_wt [768 * 1024];    // W^T hi|lo
// head-major bf16 hi|lo QKV: [B*H][N][64] (hi d 0..31, lo 32..63)
__device__ __align__(16) __nv_bfloat16 g_qb[64 * NTOK * 64];
__device__ __align__(16) __nv_bfloat16 g_kb[64 * NTOK * 64];
__device__ __align__(16) __nv_bfloat16 g_vb[64 * NTOK * 64];
// bit masks: word bit k = allowed(col)
__device__ unsigned g_m1[BATCH * NTOK * (NTOK / 32)];   // dist == 1
__device__ unsigned g_m2[BATCH * NTOK * (NTOK / 32)];   // dist >= 1

// ---------------------------------------------------------------------------
// Common helpers
// ---------------------------------------------------------------------------
__device__ __forceinline__ unsigned smem_u32(const void* p) {
    unsigned a;
    asm("{ .reg .u64 t; cvta.to.shared.u64 t, %1; cvt.u32.u64 %0, t; }"
        : "=r"(a) : "l"(p));
    return a;
}

#define LDSM_X4(r0, r1, r2, r3, addr) \
    asm volatile("ldmatrix.sync.aligned.m8n8.x4.shared.b16 {%0,%1,%2,%3}, [%4];" \
                 : "=r"(r0), "=r"(r1), "=r"(r2), "=r"(r3) : "r"(addr))

#define LDSM_X4T(r0, r1, r2, r3, addr) \
    asm volatile("ldmatrix.sync.aligned.m8n8.x4.trans.shared.b16 {%0,%1,%2,%3}, [%4];" \
                 : "=r"(r0), "=r"(r1), "=r"(r2), "=r"(r3) : "r"(addr))

#define MMA16816(d, a, b0v, b1v) \
    asm volatile("mma.sync.aligned.m16n8k16.row.col.f32.bf16.bf16.f32 " \
                 "{%0,%1,%2,%3}, {%4,%5,%6,%7}, {%8,%9}, {%0,%1,%2,%3};" \
                 : "+f"((d)[0]), "+f"((d)[1]), "+f"((d)[2]), "+f"((d)[3]) \
                 : "r"((a)[0]), "r"((a)[1]), "r"((a)[2]), "r"((a)[3]), \
                   "r"(b0v), "r"(b1v))

__device__ __forceinline__ unsigned packbf2(float x, float y) {
    __nv_bfloat162 t = __floats2bfloat162_rn(x, y);
    return *reinterpret_cast<unsigned*>(&t);
}
__device__ __forceinline__ float2 unpackbf2(unsigned u) {
    __nv_bfloat162 t = *reinterpret_cast<__nv_bfloat162*>(&u);
    return make_float2(__bfloat162float(t.x), __bfloat162float(t.y));
}

// ---------------------------------------------------------------------------
// Split-precision conversion kernels (fp32 -> bf16 hi|lo)
// ---------------------------------------------------------------------------
__global__ __launch_bounds__(256) void convA_kernel(
    const float* __restrict__ s, __nv_bfloat16* __restrict__ d, int kshift)
{
    int idx = blockIdx.x * 256 + threadIdx.x;
    int K = 1 << kshift;
    int m = idx >> kshift, k = idx & (K - 1);
    float w = s[idx];
    __nv_bfloat16 hi = __float2bfloat16(w);
    float lo = w - __bfloat162float(hi);
    __nv_bfloat16* row = d + ((size_t)m << (kshift + 1));
    row[k] = hi;
    row[K + k] = __float2bfloat16(lo);
}

__global__ __launch_bounds__(256) void convW_kernel(
    const float* __restrict__ s, __nv_bfloat16* __restrict__ d, int K, int Nc)
{
    int idx = blockIdx.x * 256 + threadIdx.x;
    int k = idx / Nc, n = idx - k * Nc;
    float w = s[idx];
    __nv_bfloat16 hi = __float2bfloat16(w);
    float lo = w - __bfloat162float(hi);
    d[(size_t)n * 2 * K + k] = hi;
    d[(size_t)n * 2 * K + K + k] = __float2bfloat16(lo);
}

// qkv fp32 (N,B,768) -> head-major bf16 hi|lo
__global__ __launch_bounds__(256) void conv_qkv_kernel(
    const float* __restrict__ qkv,
    __nv_bfloat16* __restrict__ qb, __nv_bfloat16* __restrict__ kb,
    __nv_bfloat16* __restrict__ vb)
{
    int idx = blockIdx.x * 256 + threadIdx.x;        // NROWS*768
    int nb = idx / 768;
    int rest = idx - nb * 768;
    int n = nb >> 3, b = nb & 7;
    int sec = rest >> 8;
    int h = (rest >> 5) & 7;
    int d = rest & 31;
    float v = qkv[idx];
    __nv_bfloat16 hi = __float2bfloat16(v);
    float lo = v - __bfloat162float(hi);
    __nv_bfloat16* base = (sec == 0) ? qb : (sec == 1) ? kb : vb;
    size_t off = ((size_t)((b * 8 + h) * NTOK + n)) * 64 + d;
    base[off] = hi;
    base[off + 32] = __float2bfloat16(lo);
}

// dist -> bit masks (one warp per 32 cols)
__global__ __launch_bounds__(256) void mask_kernel(
    const int* __restrict__ dist, unsigned* __restrict__ m1,
    unsigned* __restrict__ m2)
{
    int gw = (blockIdx.x * 256 + threadIdx.x) >> 5;
    int lane = threadIdx.x & 31;
    int d = dist[(size_t)gw * 32 + lane];
    unsigned b1 = __ballot_sync(0xffffffffu, d == 1);
    unsigned b2 = __ballot_sync(0xffffffffu, d >= 1);
    if (lane == 0) { m1[gw] = b1; m2[gw] = b2; }
}

// ---------------------------------------------------------------------------
// HMMA bf16 GEMM (unchanged from R13, passing): C = A'[M,3K] * W'[3K,Nc] + bias
// ---------------------------------------------------------------------------
__global__ __launch_bounds__(256, 2) void hmma_gemm_kernel(
    const __nv_bfloat16* __restrict__ A2, const __nv_bfloat16* __restrict__ Wt,
    const float* __restrict__ bias, float* __restrict__ C,
    int K, int Nc, int relu)
{
    __shared__ __align__(16) char As[128 * 128];
    __shared__ __align__(16) char Bs[128 * 128];

    const int tid = threadIdx.x;
    const int wid = tid >> 5;
    const int lane = tid & 31;
    const int wm0 = (wid & 3) * 32;
    const int wn0 = (wid >> 2) * 64;
    const int mBase = blockIdx.y * 128;
    const int nBase = blockIdx.x * 128;
    const int stride2K = 2 * K;
    const int T = (3 * K) / 64;

    const unsigned asb = smem_u32(As);
    const unsigned bsb = smem_u32(Bs);

    float acc[2][8][4];
#pragma unroll
    for (int am = 0; am < 2; am++)
#pragma unroll
        for (int bn = 0; bn < 8; bn++)
#pragma unroll
            for (int c = 0; c < 4; c++) acc[am][bn][c] = 0.0f;

    const int a_row_in = lane & 15;
    const int a_blk = lane >> 4;
    const int b_q = lane >> 3;
    const int b_r = lane & 7;

    for (int t = 0; t < T; t++) {
        const int kc64 = t * 64;
        const int aoff = (kc64 < 2 * K) ? kc64 : kc64 - 2 * K;
        const int woff = (kc64 < K) ? kc64 : kc64 - K;

#pragma unroll
        for (int i = 0; i < 4; i++) {
            int idx = i * 256 + tid;
            int row = idx >> 3, ch = idx & 7;
            int sw = row * 128 + ((ch ^ (row & 7)) << 4);
            int4 va = *(const int4*)(A2 + (size_t)(mBase + row) * stride2K + aoff + ch * 8);
            *(int4*)(As + sw) = va;
            int4 vb = *(const int4*)(Wt + (size_t)(nBase + row) * stride2K + woff + ch * 8);
            *(int4*)(Bs + sw) = vb;
        }
        __syncthreads();

#pragma unroll
        for (int ks = 0; ks < 4; ks++) {
            const int kc = ks * 2;
            unsigned af[2][4];
#pragma unroll
            for (int am = 0; am < 2; am++) {
                int row = wm0 + am * 16 + a_row_in;
                unsigned addr = asb + row * 128 + (((kc + a_blk) ^ (row & 7)) << 4);
                LDSM_X4(af[am][0], af[am][1], af[am][2], af[am][3], addr);
            }
            unsigned bf[4][4];
#pragma unroll
            for (int bn2 = 0; bn2 < 4; bn2++) {
                int n_row = wn0 + bn2 * 16 + ((b_q >> 1) << 3) + b_r;
                unsigned addr = bsb + n_row * 128 + (((kc + (b_q & 1)) ^ (n_row & 7)) << 4);
                LDSM_X4(bf[bn2][0], bf[bn2][1], bf[bn2][2], bf[bn2][3], addr);
            }
#pragma unroll
            for (int am = 0; am < 2; am++)
#pragma unroll
                for (int bn2 = 0; bn2 < 4; bn2++) {
                    MMA16816(acc[am][bn2 * 2 + 0], af[am], bf[bn2][0], bf[bn2][1]);
                    MMA16816(acc[am][bn2 * 2 + 1], af[am], bf[bn2][2], bf[bn2][3]);
                }
        }
        __syncthreads();
    }

    const int gr = lane >> 2;
    const int gc = (lane & 3) * 2;
#pragma unroll
    for (int am = 0; am < 2; am++) {
#pragma unroll
        for (int bn = 0; bn < 8; bn++) {
            int col = nBase + wn0 + bn * 8 + gc;
            float b0 = bias[col], b1 = bias[col + 1];
            int row0 = mBase + wm0 + am * 16 + gr;
            float2 v0 = make_float2(acc[am][bn][0] + b0, acc[am][bn][1] + b1);
            float2 v1 = make_float2(acc[am][bn][2] + b0, acc[am][bn][3] + b1);
            if (relu) {
                v0.x = fmaxf(v0.x, 0.0f); v0.y = fmaxf(v0.y, 0.0f);
                v1.x = fmaxf(v1.x, 0.0f); v1.y = fmaxf(v1.y, 0.0f);
            }
            *(float2*)(C + (size_t)row0 * Nc + col) = v0;
            *(float2*)(C + (size_t)(row0 + 8) * Nc + col) = v1;
        }
    }
}

// ---------------------------------------------------------------------------
// HMMA flash attention.  grid = (N/128, B*H), 256 threads = 8 warps x 16 rows.
// S = Qh*Kh + Ql*Kh + Qh*Kl (6 k16 steps);  O = Ph*Vh + Pl*Vh + Ph*Vl.
// Softmax fp32 in C-fragment registers; P repacked in-register to A-fragments.
// Epilogue writes O as bf16 hi|lo directly into GEMM A-operand layout (abf).
// ---------------------------------------------------------------------------
#define QTA 128
#define KTA 64

__global__ __launch_bounds__(256) void attn_mma_kernel(
    const __nv_bfloat16* __restrict__ Qb, const __nv_bfloat16* __restrict__ Kb,
    const __nv_bfloat16* __restrict__ Vb,
    const unsigned* __restrict__ m1, const unsigned* __restrict__ m2,
    __nv_bfloat16* __restrict__ oabf)
{
    __shared__ __align__(16) char Qs[128 * 128];
    __shared__ __align__(16) char Ks[64 * 128];
    __shared__ __align__(16) char Vs[64 * 128];

    const int tid = threadIdx.x;
    const int wid = tid >> 5;
    const int lane = tid & 31;
    const int bh = blockIdx.y;
    const int b = bh >> 3;
    const int h = bh & 7;
    const int qbase = blockIdx.x * QTA;
    const int m0 = wid * 16;
    const int gr = lane >> 2;
    const int gc = lane & 3;
    const int mtype = (h < 2) ? 1 : (h < 6) ? 2 : 0;
    const unsigned* mwsel = (mtype == 1) ? m1 : m2;
    const float SCALE = 0.17677669529663687f;   // 1/sqrt(32)

    const unsigned qsb = smem_u32(Qs);
    const unsigned ksb = smem_u32(Ks);
    const unsigned vsb = smem_u32(Vs);

    // ---- load Q tile (once): 128 rows x 64 bf16, swizzled ----
    const __nv_bfloat16* Qg = Qb + ((size_t)bh * NTOK + qbase) * 64;
#pragma unroll
    for (int i = 0; i < 4; i++) {
        int idx = i * 256 + tid;
        int row = idx >> 3, ch = idx & 7;
        int4 v = *(const int4*)(Qg + row * 64 + ch * 8);
        *(int4*)(Qs + row * 128 + ((ch ^ (row & 7)) << 4)) = v;
    }

    float oacc[4][4];
#pragma unroll
    for (int e = 0; e < 4; e++)
#pragma unroll
        for (int c = 0; c < 4; c++) oacc[e][c] = 0.0f;
    float mrun0 = -1e30f, mrun1 = -1e30f, lrun0 = 0.0f, lrun1 = 0.0f;

    const int rowa = m0 + (lane & 15);
    const int ablk = lane >> 4;

    for (int kt = 0; kt < NTOK / KTA; kt++) {
        const int kb = kt * KTA;
        __syncthreads();
        // ---- load K/V tiles: 64 rows x 64 bf16 each, swizzled ----
        const __nv_bfloat16* Kg = Kb + ((size_t)bh * NTOK + kb) * 64;
        const __nv_bfloat16* Vg = Vb + ((size_t)bh * NTOK + kb) * 64;
#pragma unroll
        for (int i = 0; i < 2; i++) {
            int idx = i * 256 + tid;
            int row = idx >> 3, ch = idx & 7;
            int sw = row * 128 + ((ch ^ (row & 7)) << 4);
            *(int4*)(Ks + sw) = *(const int4*)(Kg + row * 64 + ch * 8);
            *(int4*)(Vs + sw) = *(const int4*)(Vg + row * 64 + ch * 8);
        }
        __syncthreads();

        // ---- mask words for this thread's 2 rows ----
        unsigned wr[2][2];
        if (mtype) {
#pragma unroll
            for (int r = 0; r < 2; r++) {
                int row = qbase + m0 + gr + r * 8;
                const unsigned* p = mwsel + ((size_t)b * NTOK + row) * (NTOK / 32) + (kb >> 5);
                wr[r][0] = p[0];
                wr[r][1] = p[1];
            }
        }

        // ---- S = Q K^T (split, 6 k16 steps) ----
        float sacc[8][4];
#pragma unroll
        for (int j = 0; j < 8; j++)
#pragma unroll
            for (int c = 0; c < 4; c++) sacc[j][c] = 0.0f;

        const int steps_a[6] = {0, 2, 4, 6, 0, 2};
        const int steps_b[6] = {0, 2, 0, 2, 4, 6};
#pragma unroll
        for (int s = 0; s < 6; s++) {
            unsigned aq[4];
            unsigned aaddr = qsb + rowa * 128 + (((steps_a[s] + ablk) ^ (rowa & 7)) << 4);
            LDSM_X4(aq[0], aq[1], aq[2], aq[3], aaddr);
            const int cc = steps_b[s] + ((lane >> 3) & 1);
#pragma unroll
            for (int j = 0; j < 8; j += 2) {
                int rowk = 8 * j + ((lane >> 4) << 3) + (lane & 7);
                unsigned kaddr = ksb + rowk * 128 + ((cc ^ (rowk & 7)) << 4);
                unsigned kf0, kf1, kf2, kf3;
                LDSM_X4(kf0, kf1, kf2, kf3, kaddr);
                MMA16816(sacc[j], aq, kf0, kf1);
                MMA16816(sacc[j + 1], aq, kf2, kf3);
            }
        }

        // ---- scale + mask ----
#pragma unroll
        for (int j = 0; j < 8; j++) {
            if (mtype) {
                int col0 = 8 * j + 2 * gc;
                int wi = col0 >> 5, sh = col0 & 31;
                sacc[j][0] = ((wr[0][wi] >> sh) & 1)       ? sacc[j][0] * SCALE : -1e30f;
                sacc[j][1] = ((wr[0][wi] >> (sh + 1)) & 1) ? sacc[j][1] * SCALE : -1e30f;
                sacc[j][2] = ((wr[1][wi] >> sh) & 1)       ? sacc[j][2] * SCALE : -1e30f;
                sacc[j][3] = ((wr[1][wi] >> (sh + 1)) & 1) ? sacc[j][3] * SCALE : -1e30f;
            } else {
                sacc[j][0] *= SCALE; sacc[j][1] *= SCALE;
                sacc[j][2] *= SCALE; sacc[j][3] *= SCALE;
            }
        }

        // ---- online softmax (rows gr, gr+8; reduce across 4 lanes) ----
        float tm0 = -1e30f, tm1 = -1e30f;
#pragma unroll
        for (int j = 0; j < 8; j++) {
            tm0 = fmaxf(tm0, fmaxf(sacc[j][0], sacc[j][1]));
            tm1 = fmaxf(tm1, fmaxf(sacc[j][2], sacc[j][3]));
        }
        tm0 = fmaxf(tm0, __shfl_xor_sync(0xffffffffu, tm0, 1));
        tm0 = fmaxf(tm0, __shfl_xor_sync(0xffffffffu, tm0, 2));
        tm1 = fmaxf(tm1, __shfl_xor_sync(0xffffffffu, tm1, 1));
        tm1 = fmaxf(tm1, __shfl_xor_sync(0xffffffffu, tm1, 2));

        float mn0 = fmaxf(mrun0, tm0);
        float mn1 = fmaxf(mrun1, tm1);
        float a0 = __expf(mrun0 - mn0);
        float a1 = __expf(mrun1 - mn1);
        mrun0 = mn0; mrun1 = mn1;

        float rs0 = 0.0f, rs1 = 0.0f;
#pragma unroll
        for (int j = 0; j < 8; j++) {
            sacc[j][0] = (sacc[j][0] < -1e29f) ? 0.0f : __expf(sacc[j][0] - mn0);
            sacc[j][1] = (sacc[j][1] < -1e29f) ? 0.0f : __expf(sacc[j][1] - mn0);
            sacc[j][2] = (sacc[j][2] < -1e29f) ? 0.0f : __expf(sacc[j][2] - mn1);
            sacc[j][3] = (sacc[j][3] < -1e29f) ? 0.0f : __expf(sacc[j][3] - mn1);
            rs0 += sacc[j][0] + sacc[j][1];
            rs1 += sacc[j][2] + sacc[j][3];
        }
        rs0 += __shfl_xor_sync(0xffffffffu, rs0, 1);
        rs0 += __shfl_xor_sync(0xffffffffu, rs0, 2);
        rs1 += __shfl_xor_sync(0xffffffffu, rs1, 1);
        rs1 += __shfl_xor_sync(0xffffffffu, rs1, 2);
        lrun0 = lrun0 * a0 + rs0;
        lrun1 = lrun1 * a1 + rs1;

#pragma unroll
        for (int e = 0; e < 4; e++) {
            oacc[e][0] *= a0; oacc[e][1] *= a0;
            oacc[e][2] *= a1; oacc[e][3] *= a1;
        }

        // ---- O += P V (split) ----
#pragma unroll
        for (int t = 0; t < 4; t++) {
            const int j0 = 2 * t, j1 = 2 * t + 1;
            unsigned ah[4], al[4];
            {
                unsigned h0 = packbf2(sacc[j0][0], sacc[j0][1]);
                unsigned h1 = packbf2(sacc[j0][2], sacc[j0][3]);
                unsigned h2 = packbf2(sacc[j1][0], sacc[j1][1]);
                unsigned h3 = packbf2(sacc[j1][2], sacc[j1][3]);
                ah[0] = h0; ah[1] = h1; ah[2] = h2; ah[3] = h3;
                float2 f0 = unpackbf2(h0), f1 = unpackbf2(h1);
                float2 f2 = unpackbf2(h2), f3 = unpackbf2(h3);
                al[0] = packbf2(sacc[j0][0] - f0.x, sacc[j0][1] - f0.y);
                al[1] = packbf2(sacc[j0][2] - f1.x, sacc[j0][3] - f1.y);
                al[2] = packbf2(sacc[j1][0] - f2.x, sacc[j1][1] - f2.y);
                al[3] = packbf2(sacc[j1][2] - f3.x, sacc[j1][3] - f3.y);
            }
            const int rowv = 16 * t + ((lane >> 3) & 1) * 8 + (lane & 7);
#pragma unroll
            for (int ep = 0; ep < 4; ep += 2) {
                // V hi (chunks ep, ep+1)
                unsigned cch = ep + (lane >> 4);
                unsigned vaddr = vsb + rowv * 128 + ((cch ^ (rowv & 7)) << 4);
                unsigned v0, v1, v2, v3;
                LDSM_X4T(v0, v1, v2, v3, vaddr);
                MMA16816(oacc[ep], ah, v0, v1);
                MMA16816(oacc[ep], al, v0, v1);
                MMA16816(oacc[ep + 1], ah, v2, v3);
                MMA16816(oacc[ep + 1], al, v2, v3);
                // V lo (chunks 4+ep, 4+ep+1)
                unsigned ccl = 4 + ep + (lane >> 4);
                unsigned laddr = vsb + rowv * 128 + ((ccl ^ (rowv & 7)) << 4);
                unsigned u0, u1, u2, u3;
                LDSM_X4T(u0, u1, u2, u3, laddr);
                MMA16816(oacc[ep], ah, u0, u1);
                MMA16816(oacc[ep + 1], ah, u2, u3);
            }
        }
    }

    // ---- epilogue: normalize, write bf16 hi|lo into abf (K=256 layout) ----
    const float inv0 = 1.0f / lrun0;
    const float inv1 = 1.0f / lrun1;
    const int n0 = qbase + m0 + gr;
#pragma unroll
    for (int e = 0; e < 4; e++) {
        int col = h * 32 + 8 * e + 2 * gc;
        {
            float x0 = oacc[e][0] * inv0, x1 = oacc[e][1] * inv0;
            unsigned hp = packbf2(x0, x1);
            float2 hf = unpackbf2(hp);
            unsigned lp = packbf2(x0 - hf.x, x1 - hf.y);
            size_t base = ((size_t)(n0 * BATCH + b)) * 512 + col;
            *(unsigned*)(oabf + base) = hp;
            *(unsigned*)(oabf + base + 256) = lp;
        }
        {
            float x0 = oacc[e][2] * inv1, x1 = oacc[e][3] * inv1;
            unsigned hp = packbf2(x0, x1);
            float2 hf = unpackbf2(hp);
            unsigned lp = packbf2(x0 - hf.x, x1 - hf.y);
            size_t base = ((size_t)((n0 + 8) * BATCH + b)) * 512 + col;
            *(unsigned*)(oabf + base) = hp;
            *(unsigned*)(oabf + base + 256) = lp;
        }
    }
}

// ---------------------------------------------------------------------------
// PE denominator table + embed
// ---------------------------------------------------------------------------
__global__ void pe_table_kernel(float* den) {
    int k = threadIdx.x;
    float e = (float)(2 * (k >> 1)) / 256.0f;
    den[k] = (float)pow(10000.0, (double)e);
}

__global__ __launch_bounds__(256) void add_pe_kernel(
    const float* __restrict__ nodes, const float* __restrict__ den,
    float* __restrict__ out)
{
    int idx = blockIdx.x * 256 + threadIdx.x;
    int n = idx >> 11;
    int k = idx & 255;
    float ang = (float)n / den[k];
    double sv = (k & 1) ? cos((double)ang) : sin((double)ang);
    out[idx] = nodes[idx] + (float)sv;
}

// ---------------------------------------------------------------------------
// LayerNorm over HID=256 per row; optional residual: out = LN(y + res)
// ---------------------------------------------------------------------------
__global__ __launch_bounds__(256) void ln_kernel(
    const float* __restrict__ y, const float* __restrict__ res,
    const float* __restrict__ g, const float* __restrict__ bt,
    float* __restrict__ out)
{
    __shared__ float red[8];
    const int r = blockIdx.x;
    const int c = threadIdx.x;

    float v = y[(size_t)r * HIDW + c];
    if (res) v += res[(size_t)r * HIDW + c];

    float s = v;
#pragma unroll
    for (int off = 16; off; off >>= 1) s += __shfl_xor_sync(0xffffffffu, s, off);
    if ((c & 31) == 0) red[c >> 5] = s;
    __syncthreads();
    float tot = 0.0f;
#pragma unroll
    for (int i = 0; i < 8; i++) tot += red[i];
    float mu = tot * (1.0f / HIDW);

    float d = v - mu;
    float s2 = d * d;
#pragma unroll
    for (int off = 16; off; off >>= 1) s2 += __shfl_xor_sync(0xffffffffu, s2, off);
    __syncthreads();
    if ((c & 31) == 0) red[c >> 5] = s2;
    __syncthreads();
    float tv = 0.0f;
#pragma unroll
    for (int i = 0; i < 8; i++) tv += red[i];
    float var = tv * (1.0f / HIDW);

    out[(size_t)r * HIDW + c] = d * rsqrtf(var + LEPS) * g[c] + bt[c];
}

// ---------------------------------------------------------------------------
// Final batch-norm over B=8 at position n=0
// ---------------------------------------------------------------------------
__global__ __launch_bounds__(256) void bn_final_kernel(
    const float* __restrict__ x, const float* __restrict__ g,
    const float* __restrict__ bt, float* __restrict__ out)
{
    int c = threadIdx.x;
    float v[BATCH];
    float mu = 0.0f;
#pragma unroll
    for (int b = 0; b < BATCH; b++) {
        v[b] = x[(size_t)b * HIDW + c];
        mu += v[b];
    }
    mu *= (1.0f / BATCH);
    float var = 0.0f;
#pragma unroll
    for (int b = 0; b < BATCH; b++) {
        float d = v[b] - mu;
        var += d * d;
    }
    var *= (1.0f / BATCH);
    float rs = rsqrtf(var + LEPS);
#pragma unroll
    for (int b = 0; b < BATCH; b++)
        out[b * HIDW + c] = (v[b] - mu) * rs * g[c] + bt[c];
}

// ---------------------------------------------------------------------------
// GEMM wrapper: Afp32==nullptr means abf is already filled (pre-converted)
// ---------------------------------------------------------------------------
static void tc_gemm(const float* Afp32, const float* W, const float* bias,
                    float* C, int K, int Nc, int relu,
                    __nv_bfloat16* abf, __nv_bfloat16* wt)
{
    if (Afp32) {
        int kshift = (K == 256) ? 8 : 9;
        convA_kernel<<<(NROWS * K) / 256, 256>>>(Afp32, abf, kshift);
    }
    convW_kernel<<<(K * Nc) / 256, 256>>>(W, wt, K, Nc);
    hmma_gemm_kernel<<<dim3(Nc / 128, NROWS / 128), 256>>>(
        abf, wt, bias, C, K, Nc, relu);
}

// ---------------------------------------------------------------------------
// Launch
// ---------------------------------------------------------------------------
extern "C" void kernel_launch(void* const* d_in, const int* in_sizes, int n_in,
                              void* d_out, int out_size)
{
    const float* nodes   = (const float*)d_in[0];
    const int*   dist    = (const int*)  d_in[1];
    const float* W_in    = (const float*)d_in[2];
    const float* b_in    = (const float*)d_in[3];
    const float* ln_in_g = (const float*)d_in[4];
    const float* ln_in_b = (const float*)d_in[5];
    const float* Wqkv    = (const float*)d_in[6];
    const float* bqkv    = (const float*)d_in[7];
    const float* Wo      = (const float*)d_in[8];
    const float* bo      = (const float*)d_in[9];
    const float* ln1_g   = (const float*)d_in[10];
    const float* ln1_b   = (const float*)d_in[11];
    const float* W1      = (const float*)d_in[12];
    const float* b1      = (const float*)d_in[13];
    const float* W2      = (const float*)d_in[14];
    const float* b2      = (const float*)d_in[15];
    const float* ln2_g   = (const float*)d_in[16];
    const float* ln2_b   = (const float*)d_in[17];
    const float* bn_g    = (const float*)d_in[18];
    const float* bn_b    = (const float*)d_in[19];
    float* outp = (float*)d_out;

    float *a, *x, *y, *qkv, *den;
    __nv_bfloat16 *abf, *wt, *qb, *kb, *vb;
    unsigned *m1, *m2;
    cudaGetSymbolAddress((void**)&a,   g_a);
    cudaGetSymbolAddress((void**)&x,   g_x);
    cudaGetSymbolAddress((void**)&y,   g_y);
    cudaGetSymbolAddress((void**)&qkv, g_qkv);
    cudaGetSymbolAddress((void**)&den, g_den);
    cudaGetSymbolAddress((void**)&abf, g_abf);
    cudaGetSymbolAddress((void**)&wt,  g_wt);
    cudaGetSymbolAddress((void**)&qb,  g_qb);
    cudaGetSymbolAddress((void**)&kb,  g_kb);
    cudaGetSymbolAddress((void**)&vb,  g_vb);
    cudaGetSymbolAddress((void**)&m1,  g_m1);
    cudaGetSymbolAddress((void**)&m2,  g_m2);

    // 0. masks (once)
    mask_kernel<<<(BATCH * NTOK * NTOK / 32) / 8, 256>>>(dist, m1, m2);

    // 1. PE table + embed
    pe_table_kernel<<<1, 256>>>(den);
    add_pe_kernel<<<(NROWS * DIN) / 256, 256>>>(nodes, den, a);

    // 2. input projection + LN
    tc_gemm(a, W_in, b_in, y, 256, 256, 0, abf, wt);
    ln_kernel<<<NROWS, 256>>>(y, nullptr, ln_in_g, ln_in_b, x);

    // 3. transformer layers
    for (int l = 0; l < 2; l++) {
        tc_gemm(x, Wqkv + (size_t)l * 256 * 768, bqkv + l * 768, qkv,
                256, 768, 0, abf, wt);

        conv_qkv_kernel<<<(NROWS * 768) / 256, 256>>>(qkv, qb, kb, vb);
        attn_mma_kernel<<<dim3(NTOK / QTA, BATCH * NHEAD), 256>>>(
            qb, kb, vb, m1, m2, abf);

        // Wo GEMM consumes abf written by attention (no convA)
        tc_gemm(nullptr, Wo + (size_t)l * 256 * 256, bo + l * 256, y,
                256, 256, 0, abf, wt);
        ln_kernel<<<NROWS, 256>>>(y, x, ln1_g + l * 256, ln1_b + l * 256, x);

        tc_gemm(x, W1 + (size_t)l * 256 * 512, b1 + l * 512, qkv,
                256, 512, 1 /*relu*/, abf, wt);
        tc_gemm(qkv, W2 + (size_t)l * 512 * 256, b2 + l * 256, y,
                512, 256, 0, abf, wt);
        ln_kernel<<<NROWS, 256>>>(y, x, ln2_g + l * 256, ln2_b + l * 256, x);
    }

    // 4. final batch-norm of x[0]
    bn_final_kernel<<<1, 256>>>(x, bn_g, bn_b, outp);
}

// round 15
// speedup vs baseline: 1.8544x; 1.1667x over previous
#include <cuda_runtime.h>
#include <cuda_bf16.h>
#include <math.h>

// ---------------------------------------------------------------------------
// Problem constants
// ---------------------------------------------------------------------------
#define NTOK   1024
#define BATCH  8
#define DIN    256
#define HIDW   256
#define NROWS  (NTOK * BATCH)      // 8192
#define NHEAD  8
#define DH     32
#define LEPS   1e-5f

// ---------------------------------------------------------------------------
// Scratch (static device globals — no allocation allowed)
// ---------------------------------------------------------------------------
__device__ __align__(16) float g_x  [NROWS * HIDW];
__device__ __align__(16) float g_y  [NROWS * HIDW];
__device__ float g_den[DIN];
__device__ __align__(16) __nv_bfloat16 g_abf [NROWS * 512];   // A hi|lo, K=256 layout
__device__ __align__(16) __nv_bfloat16 g_abf2[NROWS * 1024];  // FFN hidden hi|lo, K=512
__device__ __align__(16) __nv_bfloat16 g_wt  [768 * 1024];    // W^T hi|lo
// head-major bf16 hi|lo QKV: [B*H][N][64] (hi d 0..31, lo 32..63)
__device__ __align__(16) __nv_bfloat16 g_qb[64 * NTOK * 64];
__device__ __align__(16) __nv_bfloat16 g_kb[64 * NTOK * 64];
__device__ __align__(16) __nv_bfloat16 g_vb[64 * NTOK * 64];
// bit masks: word bit k = allowed(col)
__device__ unsigned g_m1[BATCH * NTOK * (NTOK / 32)];   // dist == 1
__device__ unsigned g_m2[BATCH * NTOK * (NTOK / 32)];   // dist >= 1

// ---------------------------------------------------------------------------
// Common helpers
// ---------------------------------------------------------------------------
__device__ __forceinline__ unsigned smem_u32(const void* p) {
    unsigned a;
    asm("{ .reg .u64 t; cvta.to.shared.u64 t, %1; cvt.u32.u64 %0, t; }"
        : "=r"(a) : "l"(p));
    return a;
}

#define LDSM_X4(r0, r1, r2, r3, addr) \
    asm volatile("ldmatrix.sync.aligned.m8n8.x4.shared.b16 {%0,%1,%2,%3}, [%4];" \
                 : "=r"(r0), "=r"(r1), "=r"(r2), "=r"(r3) : "r"(addr))

#define LDSM_X4T(r0, r1, r2, r3, addr) \
    asm volatile("ldmatrix.sync.aligned.m8n8.x4.trans.shared.b16 {%0,%1,%2,%3}, [%4];" \
                 : "=r"(r0), "=r"(r1), "=r"(r2), "=r"(r3) : "r"(addr))

#define MMA16816(d, a, b0v, b1v) \
    asm volatile("mma.sync.aligned.m16n8k16.row.col.f32.bf16.bf16.f32 " \
                 "{%0,%1,%2,%3}, {%4,%5,%6,%7}, {%8,%9}, {%0,%1,%2,%3};" \
                 : "+f"((d)[0]), "+f"((d)[1]), "+f"((d)[2]), "+f"((d)[3]) \
                 : "r"((a)[0]), "r"((a)[1]), "r"((a)[2]), "r"((a)[3]), \
                   "r"(b0v), "r"(b1v))

#define CP_ASYNC16(dst, src) \
    asm volatile("cp.async.cg.shared.global [%0], [%1], 16;" \
                 :: "r"(dst), "l"(src))
#define CP_COMMIT() asm volatile("cp.async.commit_group;" ::: "memory")
#define CP_WAIT1()  asm volatile("cp.async.wait_group 1;" ::: "memory")

__device__ __forceinline__ unsigned packbf2(float x, float y) {
    __nv_bfloat162 t = __floats2bfloat162_rn(x, y);
    return *reinterpret_cast<unsigned*>(&t);
}
__device__ __forceinline__ float2 unpackbf2(unsigned u) {
    __nv_bfloat162 t = *reinterpret_cast<__nv_bfloat162*>(&u);
    return make_float2(__bfloat162float(t.x), __bfloat162float(t.y));
}
// write (x0,x1) as hi pair at p[0], lo pair at p[ofs]
__device__ __forceinline__ void split_pair(__nv_bfloat16* p, int ofs,
                                           float x0, float x1) {
    unsigned hp = packbf2(x0, x1);
    float2 hf = unpackbf2(hp);
    unsigned lp = packbf2(x0 - hf.x, x1 - hf.y);
    *(unsigned*)p = hp;
    *(unsigned*)(p + ofs) = lp;
}

// ---------------------------------------------------------------------------
// convW: W [K, Nc] row-major -> Wt [Nc, 2K] bf16 (hi cols [0,K), lo [K,2K))
// ---------------------------------------------------------------------------
__global__ __launch_bounds__(256) void convW_kernel(
    const float* __restrict__ s, __nv_bfloat16* __restrict__ d, int K, int Nc)
{
    int idx = blockIdx.x * 256 + threadIdx.x;
    int k = idx / Nc, n = idx - k * Nc;
    float w = s[idx];
    __nv_bfloat16 hi = __float2bfloat16(w);
    float lo = w - __bfloat162float(hi);
    d[(size_t)n * 2 * K + k] = hi;
    d[(size_t)n * 2 * K + K + k] = __float2bfloat16(lo);
}

// dist -> bit masks (one warp per 32 cols)
__global__ __launch_bounds__(256) void mask_kernel(
    const int* __restrict__ dist, unsigned* __restrict__ m1,
    unsigned* __restrict__ m2)
{
    int gw = (blockIdx.x * 256 + threadIdx.x) >> 5;
    int lane = threadIdx.x & 31;
    int d = dist[(size_t)gw * 32 + lane];
    unsigned b1 = __ballot_sync(0xffffffffu, d == 1);
    unsigned b2 = __ballot_sync(0xffffffffu, d >= 1);
    if (lane == 0) { m1[gw] = b1; m2[gw] = b2; }
}

// ---------------------------------------------------------------------------
// HMMA bf16 GEMM, 2-stage cp.async pipeline.
// C = A'[M,3K] * W'[3K,Nc] + bias   (virtual K' = 3K, Al*Wl dropped)
// Epilogue modes: 0 = fp32 C; 1 = ReLU + hi|lo split into osplit (K=512
// layout, row stride 1024); 2 = head-major qkv hi|lo into qb/kb/vb.
// ---------------------------------------------------------------------------
#define STG_BYTES 32768   // per stage: As 16KB + Bs 16KB

__global__ __launch_bounds__(256) void hmma_gemm_kernel(
    const __nv_bfloat16* __restrict__ A2, const __nv_bfloat16* __restrict__ Wt,
    const float* __restrict__ bias, float* __restrict__ C,
    __nv_bfloat16* __restrict__ osplit,
    __nv_bfloat16* __restrict__ qb, __nv_bfloat16* __restrict__ kb,
    __nv_bfloat16* __restrict__ vb,
    int K, int Nc, int mode)
{
    extern __shared__ __align__(16) char sm[];

    const int tid = threadIdx.x;
    const int wid = tid >> 5;
    const int lane = tid & 31;
    const int wm0 = (wid & 3) * 32;
    const int wn0 = (wid >> 2) * 64;
    const int mBase = blockIdx.y * 128;
    const int nBase = blockIdx.x * 128;
    const int stride2K = 2 * K;
    const int T = (3 * K) / 64;

    const unsigned smb = smem_u32(sm);

    float acc[2][8][4];
#pragma unroll
    for (int am = 0; am < 2; am++)
#pragma unroll
        for (int bn = 0; bn < 8; bn++)
#pragma unroll
            for (int c = 0; c < 4; c++) acc[am][bn][c] = 0.0f;

    const int ld_row = tid >> 1;            // 0..127  (2 chunks per thread pass)
    const int a_row_in = lane & 15;
    const int a_blk = lane >> 4;
    const int b_q = lane >> 3;
    const int b_r = lane & 7;

    // per-tile loader: 1024 int4 per operand, 4 int4/thread each
    auto load_tile = [&](int t, int stage) {
        const int kc64 = t * 64;
        const int aoff = (kc64 < 2 * K) ? kc64 : kc64 - 2 * K;
        const int woff = (kc64 < K) ? kc64 : kc64 - K;
        const unsigned ab = smb + stage * STG_BYTES;
        const unsigned bb = ab + 16384;
#pragma unroll
        for (int i = 0; i < 4; i++) {
            int idx = i * 256 + tid;
            int row = idx >> 3, ch = idx & 7;
            unsigned sw = row * 128 + ((ch ^ (row & 7)) << 4);
            CP_ASYNC16(ab + sw, A2 + (size_t)(mBase + row) * stride2K + aoff + ch * 8);
            CP_ASYNC16(bb + sw, Wt + (size_t)(nBase + row) * stride2K + woff + ch * 8);
        }
    };

    load_tile(0, 0);
    CP_COMMIT();

    for (int t = 0; t < T; t++) {
        if (t + 1 < T) load_tile(t + 1, (t + 1) & 1);
        CP_COMMIT();
        CP_WAIT1();
        __syncthreads();

        const unsigned asb = smb + (t & 1) * STG_BYTES;
        const unsigned bsb = asb + 16384;

#pragma unroll
        for (int ks = 0; ks < 4; ks++) {
            const int kc = ks * 2;
            unsigned af[2][4];
#pragma unroll
            for (int am = 0; am < 2; am++) {
                int row = wm0 + am * 16 + a_row_in;
                unsigned addr = asb + row * 128 + (((kc + a_blk) ^ (row & 7)) << 4);
                LDSM_X4(af[am][0], af[am][1], af[am][2], af[am][3], addr);
            }
            unsigned bf[4][4];
#pragma unroll
            for (int bn2 = 0; bn2 < 4; bn2++) {
                int n_row = wn0 + bn2 * 16 + ((b_q >> 1) << 3) + b_r;
                unsigned addr = bsb + n_row * 128 + (((kc + (b_q & 1)) ^ (n_row & 7)) << 4);
                LDSM_X4(bf[bn2][0], bf[bn2][1], bf[bn2][2], bf[bn2][3], addr);
            }
#pragma unroll
            for (int am = 0; am < 2; am++)
#pragma unroll
                for (int bn2 = 0; bn2 < 4; bn2++) {
                    MMA16816(acc[am][bn2 * 2 + 0], af[am], bf[bn2][0], bf[bn2][1]);
                    MMA16816(acc[am][bn2 * 2 + 1], af[am], bf[bn2][2], bf[bn2][3]);
                }
        }
        __syncthreads();
    }

    // ---- epilogue ----
    const int gr = lane >> 2;
    const int gc2 = (lane & 3) * 2;
#pragma unroll
    for (int am = 0; am < 2; am++) {
#pragma unroll
        for (int bn = 0; bn < 8; bn++) {
            int col = nBase + wn0 + bn * 8 + gc2;
            float b0 = bias[col], b1 = bias[col + 1];
            int row0 = mBase + wm0 + am * 16 + gr;
            float v00 = acc[am][bn][0] + b0, v01 = acc[am][bn][1] + b1;
            float v10 = acc[am][bn][2] + b0, v11 = acc[am][bn][3] + b1;
            if (mode == 0) {
                *(float2*)(C + (size_t)row0 * Nc + col) = make_float2(v00, v01);
                *(float2*)(C + (size_t)(row0 + 8) * Nc + col) = make_float2(v10, v11);
            } else if (mode == 1) {
                v00 = fmaxf(v00, 0.0f); v01 = fmaxf(v01, 0.0f);
                v10 = fmaxf(v10, 0.0f); v11 = fmaxf(v11, 0.0f);
                split_pair(osplit + (size_t)row0 * 1024 + col, 512, v00, v01);
                split_pair(osplit + (size_t)(row0 + 8) * 1024 + col, 512, v10, v11);
            } else {
                // qkv head-major: col -> (sec, h, d); row -> (n, b)
                int sec = col >> 8;
                int h = (col >> 5) & 7;
                int d = col & 31;
                __nv_bfloat16* bp = (sec == 0) ? qb : (sec == 1) ? kb : vb;
                int n0 = row0 >> 3, bb0 = row0 & 7;
                split_pair(bp + ((size_t)((bb0 * 8 + h) * NTOK + n0)) * 64 + d,
                           32, v00, v01);
                int n1 = (row0 + 8) >> 3, bb1 = (row0 + 8) & 7;
                split_pair(bp + ((size_t)((bb1 * 8 + h) * NTOK + n1)) * 64 + d,
                           32, v10, v11);
            }
        }
    }
}

// ---------------------------------------------------------------------------
// HMMA flash attention (unchanged from R14, passing).
// ---------------------------------------------------------------------------
#define QTA 128
#define KTA 64

__global__ __launch_bounds__(256) void attn_mma_kernel(
    const __nv_bfloat16* __restrict__ Qb, const __nv_bfloat16* __restrict__ Kb,
    const __nv_bfloat16* __restrict__ Vb,
    const unsigned* __restrict__ m1, const unsigned* __restrict__ m2,
    __nv_bfloat16* __restrict__ oabf)
{
    __shared__ __align__(16) char Qs[128 * 128];
    __shared__ __align__(16) char Ks[64 * 128];
    __shared__ __align__(16) char Vs[64 * 128];

    const int tid = threadIdx.x;
    const int wid = tid >> 5;
    const int lane = tid & 31;
    const int bh = blockIdx.y;
    const int b = bh >> 3;
    const int h = bh & 7;
    const int qbase = blockIdx.x * QTA;
    const int m0 = wid * 16;
    const int gr = lane >> 2;
    const int gc = lane & 3;
    const int mtype = (h < 2) ? 1 : (h < 6) ? 2 : 0;
    const unsigned* mwsel = (mtype == 1) ? m1 : m2;
    const float SCALE = 0.17677669529663687f;   // 1/sqrt(32)

    const unsigned qsb = smem_u32(Qs);
    const unsigned ksb = smem_u32(Ks);
    const unsigned vsb = smem_u32(Vs);

    const __nv_bfloat16* Qg = Qb + ((size_t)bh * NTOK + qbase) * 64;
#pragma unroll
    for (int i = 0; i < 4; i++) {
        int idx = i * 256 + tid;
        int row = idx >> 3, ch = idx & 7;
        int4 v = *(const int4*)(Qg + row * 64 + ch * 8);
        *(int4*)(Qs + row * 128 + ((ch ^ (row & 7)) << 4)) = v;
    }

    float oacc[4][4];
#pragma unroll
    for (int e = 0; e < 4; e++)
#pragma unroll
        for (int c = 0; c < 4; c++) oacc[e][c] = 0.0f;
    float mrun0 = -1e30f, mrun1 = -1e30f, lrun0 = 0.0f, lrun1 = 0.0f;

    const int rowa = m0 + (lane & 15);
    const int ablk = lane >> 4;

    for (int kt = 0; kt < NTOK / KTA; kt++) {
        const int kb = kt * KTA;
        __syncthreads();
        const __nv_bfloat16* Kg = Kb + ((size_t)bh * NTOK + kb) * 64;
        const __nv_bfloat16* Vg = Vb + ((size_t)bh * NTOK + kb) * 64;
#pragma unroll
        for (int i = 0; i < 2; i++) {
            int idx = i * 256 + tid;
            int row = idx >> 3, ch = idx & 7;
            int sw = row * 128 + ((ch ^ (row & 7)) << 4);
            *(int4*)(Ks + sw) = *(const int4*)(Kg + row * 64 + ch * 8);
            *(int4*)(Vs + sw) = *(const int4*)(Vg + row * 64 + ch * 8);
        }
        __syncthreads();

        unsigned wr[2][2];
        if (mtype) {
#pragma unroll
            for (int r = 0; r < 2; r++) {
                int row = qbase + m0 + gr + r * 8;
                const unsigned* p = mwsel + ((size_t)b * NTOK + row) * (NTOK / 32) + (kb >> 5);
                wr[r][0] = p[0];
                wr[r][1] = p[1];
            }
        }

        float sacc[8][4];
#pragma unroll
        for (int j = 0; j < 8; j++)
#pragma unroll
            for (int c = 0; c < 4; c++) sacc[j][c] = 0.0f;

        const int steps_a[6] = {0, 2, 4, 6, 0, 2};
        const int steps_b[6] = {0, 2, 0, 2, 4, 6};
#pragma unroll
        for (int s = 0; s < 6; s++) {
            unsigned aq[4];
            unsigned aaddr = qsb + rowa * 128 + (((steps_a[s] + ablk) ^ (rowa & 7)) << 4);
            LDSM_X4(aq[0], aq[1], aq[2], aq[3], aaddr);
            const int cc = steps_b[s] + ((lane >> 3) & 1);
#pragma unroll
            for (int j = 0; j < 8; j += 2) {
                int rowk = 8 * j + ((lane >> 4) << 3) + (lane & 7);
                unsigned kaddr = ksb + rowk * 128 + ((cc ^ (rowk & 7)) << 4);
                unsigned kf0, kf1, kf2, kf3;
                LDSM_X4(kf0, kf1, kf2, kf3, kaddr);
                MMA16816(sacc[j], aq, kf0, kf1);
                MMA16816(sacc[j + 1], aq, kf2, kf3);
            }
        }

#pragma unroll
        for (int j = 0; j < 8; j++) {
            if (mtype) {
                int col0 = 8 * j + 2 * gc;
                int wi = col0 >> 5, sh = col0 & 31;
                sacc[j][0] = ((wr[0][wi] >> sh) & 1)       ? sacc[j][0] * SCALE : -1e30f;
                sacc[j][1] = ((wr[0][wi] >> (sh + 1)) & 1) ? sacc[j][1] * SCALE : -1e30f;
                sacc[j][2] = ((wr[1][wi] >> sh) & 1)       ? sacc[j][2] * SCALE : -1e30f;
                sacc[j][3] = ((wr[1][wi] >> (sh + 1)) & 1) ? sacc[j][3] * SCALE : -1e30f;
            } else {
                sacc[j][0] *= SCALE; sacc[j][1] *= SCALE;
                sacc[j][2] *= SCALE; sacc[j][3] *= SCALE;
            }
        }

        float tm0 = -1e30f, tm1 = -1e30f;
#pragma unroll
        for (int j = 0; j < 8; j++) {
            tm0 = fmaxf(tm0, fmaxf(sacc[j][0], sacc[j][1]));
            tm1 = fmaxf(tm1, fmaxf(sacc[j][2], sacc[j][3]));
        }
        tm0 = fmaxf(tm0, __shfl_xor_sync(0xffffffffu, tm0, 1));
        tm0 = fmaxf(tm0, __shfl_xor_sync(0xffffffffu, tm0, 2));
        tm1 = fmaxf(tm1, __shfl_xor_sync(0xffffffffu, tm1, 1));
        tm1 = fmaxf(tm1, __shfl_xor_sync(0xffffffffu, tm1, 2));

        float mn0 = fmaxf(mrun0, tm0);
        float mn1 = fmaxf(mrun1, tm1);
        float a0 = __expf(mrun0 - mn0);
        float a1 = __expf(mrun1 - mn1);
        mrun0 = mn0; mrun1 = mn1;

        float rs0 = 0.0f, rs1 = 0.0f;
#pragma unroll
        for (int j = 0; j < 8; j++) {
            sacc[j][0] = (sacc[j][0] < -1e29f) ? 0.0f : __expf(sacc[j][0] - mn0);
            sacc[j][1] = (sacc[j][1] < -1e29f) ? 0.0f : __expf(sacc[j][1] - mn0);
            sacc[j][2] = (sacc[j][2] < -1e29f) ? 0.0f : __expf(sacc[j][2] - mn1);
            sacc[j][3] = (sacc[j][3] < -1e29f) ? 0.0f : __expf(sacc[j][3] - mn1);
            rs0 += sacc[j][0] + sacc[j][1];
            rs1 += sacc[j][2] + sacc[j][3];
        }
        rs0 += __shfl_xor_sync(0xffffffffu, rs0, 1);
        rs0 += __shfl_xor_sync(0xffffffffu, rs0, 2);
        rs1 += __shfl_xor_sync(0xffffffffu, rs1, 1);
        rs1 += __shfl_xor_sync(0xffffffffu, rs1, 2);
        lrun0 = lrun0 * a0 + rs0;
        lrun1 = lrun1 * a1 + rs1;

#pragma unroll
        for (int e = 0; e < 4; e++) {
            oacc[e][0] *= a0; oacc[e][1] *= a0;
            oacc[e][2] *= a1; oacc[e][3] *= a1;
        }

#pragma unroll
        for (int t = 0; t < 4; t++) {
            const int j0 = 2 * t, j1 = 2 * t + 1;
            unsigned ah[4], al[4];
            {
                unsigned h0 = packbf2(sacc[j0][0], sacc[j0][1]);
                unsigned h1 = packbf2(sacc[j0][2], sacc[j0][3]);
                unsigned h2 = packbf2(sacc[j1][0], sacc[j1][1]);
                unsigned h3 = packbf2(sacc[j1][2], sacc[j1][3]);
                ah[0] = h0; ah[1] = h1; ah[2] = h2; ah[3] = h3;
                float2 f0 = unpackbf2(h0), f1 = unpackbf2(h1);
                float2 f2 = unpackbf2(h2), f3 = unpackbf2(h3);
                al[0] = packbf2(sacc[j0][0] - f0.x, sacc[j0][1] - f0.y);
                al[1] = packbf2(sacc[j0][2] - f1.x, sacc[j0][3] - f1.y);
                al[2] = packbf2(sacc[j1][0] - f2.x, sacc[j1][1] - f2.y);
                al[3] = packbf2(sacc[j1][2] - f3.x, sacc[j1][3] - f3.y);
            }
            const int rowv = 16 * t + ((lane >> 3) & 1) * 8 + (lane & 7);
#pragma unroll
            for (int ep = 0; ep < 4; ep += 2) {
                unsigned cch = ep + (lane >> 4);
                unsigned vaddr = vsb + rowv * 128 + ((cch ^ (rowv & 7)) << 4);
                unsigned v0, v1, v2, v3;
                LDSM_X4T(v0, v1, v2, v3, vaddr);
                MMA16816(oacc[ep], ah, v0, v1);
                MMA16816(oacc[ep], al, v0, v1);
                MMA16816(oacc[ep + 1], ah, v2, v3);
                MMA16816(oacc[ep + 1], al, v2, v3);
                unsigned ccl = 4 + ep + (lane >> 4);
                unsigned laddr = vsb + rowv * 128 + ((ccl ^ (rowv & 7)) << 4);
                unsigned u0, u1, u2, u3;
                LDSM_X4T(u0, u1, u2, u3, laddr);
                MMA16816(oacc[ep], ah, u0, u1);
                MMA16816(oacc[ep + 1], ah, u2, u3);
            }
        }
    }

    const float inv0 = 1.0f / lrun0;
    const float inv1 = 1.0f / lrun1;
    const int n0 = qbase + m0 + gr;
#pragma unroll
    for (int e = 0; e < 4; e++) {
        int col = h * 32 + 8 * e + 2 * gc;
        split_pair(oabf + ((size_t)(n0 * BATCH + b)) * 512 + col, 256,
                   oacc[e][0] * inv0, oacc[e][1] * inv0);
        split_pair(oabf + ((size_t)((n0 + 8) * BATCH + b)) * 512 + col, 256,
                   oacc[e][2] * inv1, oacc[e][3] * inv1);
    }
}

// ---------------------------------------------------------------------------
// PE denominator table + fused embed+split (writes abf hi|lo directly)
// ---------------------------------------------------------------------------
__global__ void pe_table_kernel(float* den) {
    int k = threadIdx.x;
    float e = (float)(2 * (k >> 1)) / 256.0f;
    den[k] = (float)pow(10000.0, (double)e);
}

__global__ __launch_bounds__(256) void add_pe_split_kernel(
    const float* __restrict__ nodes, const float* __restrict__ den,
    __nv_bfloat16* __restrict__ abf)
{
    int idx = blockIdx.x * 256 + threadIdx.x;   // NROWS*256
    int n = idx >> 11;                          // row = n*8+b = idx>>8
    int k = idx & 255;
    float ang = (float)n / den[k];
    double sv = (k & 1) ? cos((double)ang) : sin((double)ang);
    float w = nodes[idx] + (float)sv;
    __nv_bfloat16 hi = __float2bfloat16(w);
    float lo = w - __bfloat162float(hi);
    int m = idx >> 8;
    abf[(size_t)m * 512 + k] = hi;
    abf[(size_t)m * 512 + 256 + k] = __float2bfloat16(lo);
}

// ---------------------------------------------------------------------------
// LayerNorm (+residual) fused with hi|lo split output
// ---------------------------------------------------------------------------
__global__ __launch_bounds__(256) void ln_split_kernel(
    const float* __restrict__ y, const float* __restrict__ res,
    const float* __restrict__ g, const float* __restrict__ bt,
    float* __restrict__ xout, __nv_bfloat16* __restrict__ abf)
{
    __shared__ float red[8];
    const int r = blockIdx.x;
    const int c = threadIdx.x;

    float v = y[(size_t)r * HIDW + c];
    if (res) v += res[(size_t)r * HIDW + c];

    float s = v;
#pragma unroll
    for (int off = 16; off; off >>= 1) s += __shfl_xor_sync(0xffffffffu, s, off);
    if ((c & 31) == 0) red[c >> 5] = s;
    __syncthreads();
    float tot = 0.0f;
#pragma unroll
    for (int i = 0; i < 8; i++) tot += red[i];
    float mu = tot * (1.0f / HIDW);

    float d = v - mu;
    float s2 = d * d;
#pragma unroll
    for (int off = 16; off; off >>= 1) s2 += __shfl_xor_sync(0xffffffffu, s2, off);
    __syncthreads();
    if ((c & 31) == 0) red[c >> 5] = s2;
    __syncthreads();
    float tv = 0.0f;
#pragma unroll
    for (int i = 0; i < 8; i++) tv += red[i];
    float var = tv * (1.0f / HIDW);

    float o = d * rsqrtf(var + LEPS) * g[c] + bt[c];
    xout[(size_t)r * HIDW + c] = o;
    __nv_bfloat16 hi = __float2bfloat16(o);
    abf[(size_t)r * 512 + c] = hi;
    abf[(size_t)r * 512 + 256 + c] = __float2bfloat16(o - __bfloat162float(hi));
}

// ---------------------------------------------------------------------------
// Final batch-norm over B=8 at position n=0
// ---------------------------------------------------------------------------
__global__ __launch_bounds__(256) void bn_final_kernel(
    const float* __restrict__ x, const float* __restrict__ g,
    const float* __restrict__ bt, float* __restrict__ out)
{
    int c = threadIdx.x;
    float v[BATCH];
    float mu = 0.0f;
#pragma unroll
    for (int b = 0; b < BATCH; b++) {
        v[b] = x[(size_t)b * HIDW + c];
        mu += v[b];
    }
    mu *= (1.0f / BATCH);
    float var = 0.0f;
#pragma unroll
    for (int b = 0; b < BATCH; b++) {
        float d = v[b] - mu;
        var += d * d;
    }
    var *= (1.0f / BATCH);
    float rs = rsqrtf(var + LEPS);
#pragma unroll
    for (int b = 0; b < BATCH; b++)
        out[b * HIDW + c] = (v[b] - mu) * rs * g[c] + bt[c];
}

// ---------------------------------------------------------------------------
// Launch
// ---------------------------------------------------------------------------
#define GEMM_SMEM (2 * STG_BYTES)

extern "C" void kernel_launch(void* const* d_in, const int* in_sizes, int n_in,
                              void* d_out, int out_size)
{
    const float* nodes   = (const float*)d_in[0];
    const int*   dist    = (const int*)  d_in[1];
    const float* W_in    = (const float*)d_in[2];
    const float* b_in    = (const float*)d_in[3];
    const float* ln_in_g = (const float*)d_in[4];
    const float* ln_in_b = (const float*)d_in[5];
    const float* Wqkv    = (const float*)d_in[6];
    const float* bqkv    = (const float*)d_in[7];
    const float* Wo      = (const float*)d_in[8];
    const float* bo      = (const float*)d_in[9];
    const float* ln1_g   = (const float*)d_in[10];
    const float* ln1_b   = (const float*)d_in[11];
    const float* W1      = (const float*)d_in[12];
    const float* b1      = (const float*)d_in[13];
    const float* W2      = (const float*)d_in[14];
    const float* b2      = (const float*)d_in[15];
    const float* ln2_g   = (const float*)d_in[16];
    const float* ln2_b   = (const float*)d_in[17];
    const float* bn_g    = (const float*)d_in[18];
    const float* bn_b    = (const float*)d_in[19];
    float* outp = (float*)d_out;

    float *x, *y, *den;
    __nv_bfloat16 *abf, *abf2, *wt, *qb, *kb, *vb;
    unsigned *m1, *m2;
    cudaGetSymbolAddress((void**)&x,    g_x);
    cudaGetSymbolAddress((void**)&y,    g_y);
    cudaGetSymbolAddress((void**)&den,  g_den);
    cudaGetSymbolAddress((void**)&abf,  g_abf);
    cudaGetSymbolAddress((void**)&abf2, g_abf2);
    cudaGetSymbolAddress((void**)&wt,   g_wt);
    cudaGetSymbolAddress((void**)&qb,   g_qb);
    cudaGetSymbolAddress((void**)&kb,   g_kb);
    cudaGetSymbolAddress((void**)&vb,   g_vb);
    cudaGetSymbolAddress((void**)&m1,   g_m1);
    cudaGetSymbolAddress((void**)&m2,   g_m2);

    cudaFuncSetAttribute(hmma_gemm_kernel,
                         cudaFuncAttributeMaxDynamicSharedMemorySize, GEMM_SMEM);

    // 0. masks (once)
    mask_kernel<<<(BATCH * NTOK * NTOK / 32) / 8, 256>>>(dist, m1, m2);

    // 1. PE table + fused embed+split
    pe_table_kernel<<<1, 256>>>(den);
    add_pe_split_kernel<<<(NROWS * DIN) / 256, 256>>>(nodes, den, abf);

    // 2. input projection + LN(+split)
    convW_kernel<<<(256 * 256) / 256, 256>>>(W_in, wt, 256, 256);
    hmma_gemm_kernel<<<dim3(2, 64), 256, GEMM_SMEM>>>(
        abf, wt, b_in, y, nullptr, nullptr, nullptr, nullptr, 256, 256, 0);
    ln_split_kernel<<<NROWS, 256>>>(y, nullptr, ln_in_g, ln_in_b, x, abf);

    // 3. transformer layers
    for (int l = 0; l < 2; l++) {
        // QKV: fused head-major split epilogue
        convW_kernel<<<(256 * 768) / 256, 256>>>(Wqkv + (size_t)l * 256 * 768,
                                                 wt, 256, 768);
        hmma_gemm_kernel<<<dim3(6, 64), 256, GEMM_SMEM>>>(
            abf, wt, bqkv + l * 768, nullptr, nullptr, qb, kb, vb, 256, 768, 2);

        attn_mma_kernel<<<dim3(NTOK / QTA, BATCH * NHEAD), 256>>>(
            qb, kb, vb, m1, m2, abf);

        // Wo: consumes abf written by attention
        convW_kernel<<<(256 * 256) / 256, 256>>>(Wo + (size_t)l * 256 * 256,
                                                 wt, 256, 256);
        hmma_gemm_kernel<<<dim3(2, 64), 256, GEMM_SMEM>>>(
            abf, wt, bo + l * 256, y, nullptr, nullptr, nullptr, nullptr,
            256, 256, 0);
        ln_split_kernel<<<NROWS, 256>>>(y, x, ln1_g + l * 256, ln1_b + l * 256,
                                        x, abf);

        // FFN W1: ReLU + split epilogue into abf2
        convW_kernel<<<(256 * 512) / 256, 256>>>(W1 + (size_t)l * 256 * 512,
                                                 wt, 256, 512);
        hmma_gemm_kernel<<<dim3(4, 64), 256, GEMM_SMEM>>>(
            abf, wt, b1 + l * 512, nullptr, abf2, nullptr, nullptr, nullptr,
            256, 512, 1);
        // FFN W2
        convW_kernel<<<(512 * 256) / 256, 256>>>(W2 + (size_t)l * 512 * 256,
                                                 wt, 512, 256);
        hmma_gemm_kernel<<<dim3(2, 64), 256, GEMM_SMEM>>>(
            abf2, wt, b2 + l * 256, y, nullptr, nullptr, nullptr, nullptr,
            512, 256, 0);
        ln_split_kernel<<<NROWS, 256>>>(y, x, ln2_g + l * 256, ln2_b + l * 256,
                                        x, abf);
    }

    // 4. final batch-norm of x[0]
    bn_final_kernel<<<1, 256>>>(x, bn_g, bn_b, outp);
}

// round 16
// speedup vs baseline: 1.8632x; 1.0047x over previous
#include <cuda_runtime.h>
#include <cuda_bf16.h>
#include <math.h>

// ---------------------------------------------------------------------------
// Problem constants
// ---------------------------------------------------------------------------
#define NTOK   1024
#define BATCH  8
#define DIN    256
#define HIDW   256
#define NROWS  (NTOK * BATCH)      // 8192
#define NHEAD  8
#define DH     32
#define LEPS   1e-5f

// ---------------------------------------------------------------------------
// Scratch (static device globals — no allocation allowed)
// ---------------------------------------------------------------------------
__device__ __align__(16) float g_x  [NROWS * HIDW];
__device__ __align__(16) float g_y  [NROWS * HIDW];
__device__ float g_den[DIN];
__device__ __align__(16) __nv_bfloat16 g_abf [NROWS * 512];   // A hi|lo, K=256 layout
__device__ __align__(16) __nv_bfloat16 g_abf2[NROWS * 1024];  // FFN hidden hi|lo, K=512
__device__ __align__(16) __nv_bfloat16 g_wtall[2228224];      // ALL W^T hi|lo
// head-major bf16 hi|lo QKV: [B*H][N][64] (hi d 0..31, lo 32..63)
__device__ __align__(16) __nv_bfloat16 g_qb[64 * NTOK * 64];
__device__ __align__(16) __nv_bfloat16 g_kb[64 * NTOK * 64];
__device__ __align__(16) __nv_bfloat16 g_vb[64 * NTOK * 64];
// bit masks: word bit k = allowed(col)
__device__ unsigned g_m1[BATCH * NTOK * (NTOK / 32)];   // dist == 1
__device__ unsigned g_m2[BATCH * NTOK * (NTOK / 32)];   // dist >= 1

// ---------------------------------------------------------------------------
// Common helpers
// ---------------------------------------------------------------------------
__device__ __forceinline__ unsigned smem_u32(const void* p) {
    unsigned a;
    asm("{ .reg .u64 t; cvta.to.shared.u64 t, %1; cvt.u32.u64 %0, t; }"
        : "=r"(a) : "l"(p));
    return a;
}

#define LDSM_X4(r0, r1, r2, r3, addr) \
    asm volatile("ldmatrix.sync.aligned.m8n8.x4.shared.b16 {%0,%1,%2,%3}, [%4];" \
                 : "=r"(r0), "=r"(r1), "=r"(r2), "=r"(r3) : "r"(addr))

#define LDSM_X4T(r0, r1, r2, r3, addr) \
    asm volatile("ldmatrix.sync.aligned.m8n8.x4.trans.shared.b16 {%0,%1,%2,%3}, [%4];" \
                 : "=r"(r0), "=r"(r1), "=r"(r2), "=r"(r3) : "r"(addr))

#define MMA16816(d, a, b0v, b1v) \
    asm volatile("mma.sync.aligned.m16n8k16.row.col.f32.bf16.bf16.f32 " \
                 "{%0,%1,%2,%3}, {%4,%5,%6,%7}, {%8,%9}, {%0,%1,%2,%3};" \
                 : "+f"((d)[0]), "+f"((d)[1]), "+f"((d)[2]), "+f"((d)[3]) \
                 : "r"((a)[0]), "r"((a)[1]), "r"((a)[2]), "r"((a)[3]), \
                   "r"(b0v), "r"(b1v))

#define CP_ASYNC16(dst, src) \
    asm volatile("cp.async.cg.shared.global [%0], [%1], 16;" \
                 :: "r"(dst), "l"(src))
#define CP_COMMIT() asm volatile("cp.async.commit_group;" ::: "memory")
#define CP_WAIT1()  asm volatile("cp.async.wait_group 1;" ::: "memory")
#define CP_WAIT0()  asm volatile("cp.async.wait_group 0;" ::: "memory")

__device__ __forceinline__ unsigned packbf2(float x, float y) {
    __nv_bfloat162 t = __floats2bfloat162_rn(x, y);
    return *reinterpret_cast<unsigned*>(&t);
}
__device__ __forceinline__ float2 unpackbf2(unsigned u) {
    __nv_bfloat162 t = *reinterpret_cast<__nv_bfloat162*>(&u);
    return make_float2(__bfloat162float(t.x), __bfloat162float(t.y));
}
__device__ __forceinline__ void split_pair(__nv_bfloat16* p, int ofs,
                                           float x0, float x1) {
    unsigned hp = packbf2(x0, x1);
    float2 hf = unpackbf2(hp);
    unsigned lp = packbf2(x0 - hf.x, x1 - hf.y);
    *(unsigned*)p = hp;
    *(unsigned*)(p + ofs) = lp;
}

// ---------------------------------------------------------------------------
// One-shot conversion of ALL weights: W [K,Nc] -> Wt [Nc,2K] bf16 hi|lo
// ---------------------------------------------------------------------------
struct ConvJobs {
    const float* src[9];
    long dstOff[9];
    int K[9];
    int Nc[9];
    int start[10];
};

__global__ __launch_bounds__(256) void convW_all_kernel(
    ConvJobs J, __nv_bfloat16* __restrict__ d)
{
    int idx = blockIdx.x * 256 + threadIdx.x;
    int r = 0;
#pragma unroll
    for (int i = 1; i < 9; i++) if (idx >= J.start[i]) r = i;
    int li = idx - J.start[r];
    int K = J.K[r], Nc = J.Nc[r];
    int k = li / Nc, n = li - k * Nc;
    float w = J.src[r][li];
    __nv_bfloat16 hi = __float2bfloat16(w);
    float lo = w - __bfloat162float(hi);
    __nv_bfloat16* dst = d + J.dstOff[r];
    dst[(size_t)n * 2 * K + k] = hi;
    dst[(size_t)n * 2 * K + K + k] = __float2bfloat16(lo);
}

// dist -> bit masks (one warp per 32 cols)
__global__ __launch_bounds__(256) void mask_kernel(
    const int* __restrict__ dist, unsigned* __restrict__ m1,
    unsigned* __restrict__ m2)
{
    int gw = (blockIdx.x * 256 + threadIdx.x) >> 5;
    int lane = threadIdx.x & 31;
    int d = dist[(size_t)gw * 32 + lane];
    unsigned b1 = __ballot_sync(0xffffffffu, d == 1);
    unsigned b2 = __ballot_sync(0xffffffffu, d >= 1);
    if (lane == 0) { m1[gw] = b1; m2[gw] = b2; }
}

// ---------------------------------------------------------------------------
// HMMA bf16 GEMM, 2-stage cp.async pipeline, templated on BM (128 or 64).
// C = A'[M,3K] * W'[3K,Nc] + bias   (virtual K' = 3K, Al*Wl dropped)
// Epilogue modes: 0 = fp32 C; 1 = ReLU + hi|lo split into osplit (K=512
// layout); 2 = head-major qkv hi|lo into qb/kb/vb.
// ---------------------------------------------------------------------------
template<int BM>
__global__ __launch_bounds__(256) void hmma_gemm_t(
    const __nv_bfloat16* __restrict__ A2, const __nv_bfloat16* __restrict__ Wt,
    const float* __restrict__ bias, float* __restrict__ C,
    __nv_bfloat16* __restrict__ osplit,
    __nv_bfloat16* __restrict__ qb, __nv_bfloat16* __restrict__ kb,
    __nv_bfloat16* __restrict__ vb,
    int K, int Nc, int mode)
{
    extern __shared__ __align__(16) char sm[];

    constexpr int NW_M = BM / 32;          // 4 or 2
    constexpr int WN = 128 / (8 / NW_M);   // 64 or 32
    constexpr int NFRAG = WN / 8;          // 8 or 4
    constexpr int SB = BM * 128 + 16384;   // stage bytes (A + B)

    const int tid = threadIdx.x;
    const int wid = tid >> 5;
    const int lane = tid & 31;
    const int wm0 = (wid % NW_M) * 32;
    const int wn0 = (wid / NW_M) * WN;
    const int mBase = blockIdx.y * BM;
    const int nBase = blockIdx.x * 128;
    const int stride2K = 2 * K;
    const int T = (3 * K) / 64;

    const unsigned smb = smem_u32(sm);

    float acc[2][NFRAG][4];
#pragma unroll
    for (int am = 0; am < 2; am++)
#pragma unroll
        for (int bn = 0; bn < NFRAG; bn++)
#pragma unroll
            for (int c = 0; c < 4; c++) acc[am][bn][c] = 0.0f;

    const int a_row_in = lane & 15;
    const int a_blk = lane >> 4;
    const int b_q = lane >> 3;
    const int b_r = lane & 7;

    auto load_tile = [&](int t, int stage) {
        const int kc64 = t * 64;
        const int aoff = (kc64 < 2 * K) ? kc64 : kc64 - 2 * K;
        const int woff = (kc64 < K) ? kc64 : kc64 - K;
        const unsigned ab = smb + stage * SB;
        const unsigned bbs = ab + BM * 128;
#pragma unroll
        for (int i = 0; i < BM / 32; i++) {
            int idx = i * 256 + tid;
            int row = idx >> 3, ch = idx & 7;
            unsigned sw = row * 128 + ((ch ^ (row & 7)) << 4);
            CP_ASYNC16(ab + sw, A2 + (size_t)(mBase + row) * stride2K + aoff + ch * 8);
        }
#pragma unroll
        for (int i = 0; i < 4; i++) {
            int idx = i * 256 + tid;
            int row = idx >> 3, ch = idx & 7;
            unsigned sw = row * 128 + ((ch ^ (row & 7)) << 4);
            CP_ASYNC16(bbs + sw, Wt + (size_t)(nBase + row) * stride2K + woff + ch * 8);
        }
    };

    load_tile(0, 0);
    CP_COMMIT();

    for (int t = 0; t < T; t++) {
        if (t + 1 < T) {
            load_tile(t + 1, (t + 1) & 1);
            CP_COMMIT();
            CP_WAIT1();
        } else {
            CP_WAIT0();
        }
        __syncthreads();

        const unsigned asb = smb + (t & 1) * SB;
        const unsigned bsb = asb + BM * 128;

#pragma unroll
        for (int ks = 0; ks < 4; ks++) {
            const int kc = ks * 2;
            unsigned af[2][4];
#pragma unroll
            for (int am = 0; am < 2; am++) {
                int row = wm0 + am * 16 + a_row_in;
                unsigned addr = asb + row * 128 + (((kc + a_blk) ^ (row & 7)) << 4);
                LDSM_X4(af[am][0], af[am][1], af[am][2], af[am][3], addr);
            }
            unsigned bf[NFRAG / 2][4];
#pragma unroll
            for (int bn2 = 0; bn2 < NFRAG / 2; bn2++) {
                int n_row = wn0 + bn2 * 16 + ((b_q >> 1) << 3) + b_r;
                unsigned addr = bsb + n_row * 128 + (((kc + (b_q & 1)) ^ (n_row & 7)) << 4);
                LDSM_X4(bf[bn2][0], bf[bn2][1], bf[bn2][2], bf[bn2][3], addr);
            }
#pragma unroll
            for (int am = 0; am < 2; am++)
#pragma unroll
                for (int bn2 = 0; bn2 < NFRAG / 2; bn2++) {
                    MMA16816(acc[am][bn2 * 2 + 0], af[am], bf[bn2][0], bf[bn2][1]);
                    MMA16816(acc[am][bn2 * 2 + 1], af[am], bf[bn2][2], bf[bn2][3]);
                }
        }
        __syncthreads();
    }

    // ---- epilogue ----
    const int gr = lane >> 2;
    const int gc2 = (lane & 3) * 2;
#pragma unroll
    for (int am = 0; am < 2; am++) {
#pragma unroll
        for (int bn = 0; bn < NFRAG; bn++) {
            int col = nBase + wn0 + bn * 8 + gc2;
            float b0 = bias[col], b1 = bias[col + 1];
            int row0 = mBase + wm0 + am * 16 + gr;
            float v00 = acc[am][bn][0] + b0, v01 = acc[am][bn][1] + b1;
            float v10 = acc[am][bn][2] + b0, v11 = acc[am][bn][3] + b1;
            if (mode == 0) {
                *(float2*)(C + (size_t)row0 * Nc + col) = make_float2(v00, v01);
                *(float2*)(C + (size_t)(row0 + 8) * Nc + col) = make_float2(v10, v11);
            } else if (mode == 1) {
                v00 = fmaxf(v00, 0.0f); v01 = fmaxf(v01, 0.0f);
                v10 = fmaxf(v10, 0.0f); v11 = fmaxf(v11, 0.0f);
                split_pair(osplit + (size_t)row0 * 1024 + col, 512, v00, v01);
                split_pair(osplit + (size_t)(row0 + 8) * 1024 + col, 512, v10, v11);
            } else {
                int sec = col >> 8;
                int h = (col >> 5) & 7;
                int d = col & 31;
                __nv_bfloat16* bp = (sec == 0) ? qb : (sec == 1) ? kb : vb;
                int n0 = row0 >> 3, bb0 = row0 & 7;
                split_pair(bp + ((size_t)((bb0 * 8 + h) * NTOK + n0)) * 64 + d,
                           32, v00, v01);
                int n1 = (row0 + 8) >> 3, bb1 = (row0 + 8) & 7;
                split_pair(bp + ((size_t)((bb1 * 8 + h) * NTOK + n1)) * 64 + d,
                           32, v10, v11);
            }
        }
    }
}

// ---------------------------------------------------------------------------
// HMMA flash attention with 2-stage cp.async K/V pipeline.
// ---------------------------------------------------------------------------
#define QTA 128
#define KTA 64

__global__ __launch_bounds__(256) void attn_mma_kernel(
    const __nv_bfloat16* __restrict__ Qb, const __nv_bfloat16* __restrict__ Kb,
    const __nv_bfloat16* __restrict__ Vb,
    const unsigned* __restrict__ m1, const unsigned* __restrict__ m2,
    __nv_bfloat16* __restrict__ oabf)
{
    __shared__ __align__(16) char Qs[128 * 128];
    __shared__ __align__(16) char KV[2][16384];   // per stage: K 8KB | V 8KB

    const int tid = threadIdx.x;
    const int wid = tid >> 5;
    const int lane = tid & 31;
    const int bh = blockIdx.y;
    const int b = bh >> 3;
    const int h = bh & 7;
    const int qbase = blockIdx.x * QTA;
    const int m0 = wid * 16;
    const int gr = lane >> 2;
    const int gc = lane & 3;
    const int mtype = (h < 2) ? 1 : (h < 6) ? 2 : 0;
    const unsigned* mwsel = (mtype == 1) ? m1 : m2;
    const float SCALE = 0.17677669529663687f;   // 1/sqrt(32)

    const unsigned qsb = smem_u32(Qs);
    const unsigned kvb = smem_u32(KV);

    // ---- load Q tile (once), synchronous ----
    const __nv_bfloat16* Qg = Qb + ((size_t)bh * NTOK + qbase) * 64;
#pragma unroll
    for (int i = 0; i < 4; i++) {
        int idx = i * 256 + tid;
        int row = idx >> 3, ch = idx & 7;
        int4 v = *(const int4*)(Qg + row * 64 + ch * 8);
        *(int4*)(Qs + row * 128 + ((ch ^ (row & 7)) << 4)) = v;
    }

    auto loadKV = [&](int kt, int stg) {
        const __nv_bfloat16* Kg = Kb + ((size_t)bh * NTOK + kt * KTA) * 64;
        const __nv_bfloat16* Vg = Vb + ((size_t)bh * NTOK + kt * KTA) * 64;
        const unsigned kd = kvb + stg * 16384;
        const unsigned vd = kd + 8192;
#pragma unroll
        for (int i = 0; i < 2; i++) {
            int idx = i * 256 + tid;
            int row = idx >> 3, ch = idx & 7;
            unsigned sw = row * 128 + ((ch ^ (row & 7)) << 4);
            CP_ASYNC16(kd + sw, Kg + row * 64 + ch * 8);
            CP_ASYNC16(vd + sw, Vg + row * 64 + ch * 8);
        }
    };

    float oacc[4][4];
#pragma unroll
    for (int e = 0; e < 4; e++)
#pragma unroll
        for (int c = 0; c < 4; c++) oacc[e][c] = 0.0f;
    float mrun0 = -1e30f, mrun1 = -1e30f, lrun0 = 0.0f, lrun1 = 0.0f;

    const int rowa = m0 + (lane & 15);
    const int ablk = lane >> 4;

    loadKV(0, 0);
    CP_COMMIT();

    for (int kt = 0; kt < NTOK / KTA; kt++) {
        const int kb = kt * KTA;
        if (kt + 1 < NTOK / KTA) {
            loadKV(kt + 1, (kt + 1) & 1);
            CP_COMMIT();
            CP_WAIT1();
        } else {
            CP_WAIT0();
        }
        __syncthreads();

        const unsigned ksb = kvb + (kt & 1) * 16384;
        const unsigned vsb = ksb + 8192;

        unsigned wr[2][2];
        if (mtype) {
#pragma unroll
            for (int r = 0; r < 2; r++) {
                int row = qbase + m0 + gr + r * 8;
                const unsigned* p = mwsel + ((size_t)b * NTOK + row) * (NTOK / 32) + (kb >> 5);
                wr[r][0] = p[0];
                wr[r][1] = p[1];
            }
        }

        float sacc[8][4];
#pragma unroll
        for (int j = 0; j < 8; j++)
#pragma unroll
            for (int c = 0; c < 4; c++) sacc[j][c] = 0.0f;

        const int steps_a[6] = {0, 2, 4, 6, 0, 2};
        const int steps_b[6] = {0, 2, 0, 2, 4, 6};
#pragma unroll
        for (int s = 0; s < 6; s++) {
            unsigned aq[4];
            unsigned aaddr = qsb + rowa * 128 + (((steps_a[s] + ablk) ^ (rowa & 7)) << 4);
            LDSM_X4(aq[0], aq[1], aq[2], aq[3], aaddr);
            const int cc = steps_b[s] + ((lane >> 3) & 1);
#pragma unroll
            for (int j = 0; j < 8; j += 2) {
                int rowk = 8 * j + ((lane >> 4) << 3) + (lane & 7);
                unsigned kaddr = ksb + rowk * 128 + ((cc ^ (rowk & 7)) << 4);
                unsigned kf0, kf1, kf2, kf3;
                LDSM_X4(kf0, kf1, kf2, kf3, kaddr);
                MMA16816(sacc[j], aq, kf0, kf1);
                MMA16816(sacc[j + 1], aq, kf2, kf3);
            }
        }

#pragma unroll
        for (int j = 0; j < 8; j++) {
            if (mtype) {
                int col0 = 8 * j + 2 * gc;
                int wi = col0 >> 5, sh = col0 & 31;
                sacc[j][0] = ((wr[0][wi] >> sh) & 1)       ? sacc[j][0] * SCALE : -1e30f;
                sacc[j][1] = ((wr[0][wi] >> (sh + 1)) & 1) ? sacc[j][1] * SCALE : -1e30f;
                sacc[j][2] = ((wr[1][wi] >> sh) & 1)       ? sacc[j][2] * SCALE : -1e30f;
                sacc[j][3] = ((wr[1][wi] >> (sh + 1)) & 1) ? sacc[j][3] * SCALE : -1e30f;
            } else {
                sacc[j][0] *= SCALE; sacc[j][1] *= SCALE;
                sacc[j][2] *= SCALE; sacc[j][3] *= SCALE;
            }
        }

        float tm0 = -1e30f, tm1 = -1e30f;
#pragma unroll
        for (int j = 0; j < 8; j++) {
            tm0 = fmaxf(tm0, fmaxf(sacc[j][0], sacc[j][1]));
            tm1 = fmaxf(tm1, fmaxf(sacc[j][2], sacc[j][3]));
        }
        tm0 = fmaxf(tm0, __shfl_xor_sync(0xffffffffu, tm0, 1));
        tm0 = fmaxf(tm0, __shfl_xor_sync(0xffffffffu, tm0, 2));
        tm1 = fmaxf(tm1, __shfl_xor_sync(0xffffffffu, tm1, 1));
        tm1 = fmaxf(tm1, __shfl_xor_sync(0xffffffffu, tm1, 2));

        float mn0 = fmaxf(mrun0, tm0);
        float mn1 = fmaxf(mrun1, tm1);
        float a0 = __expf(mrun0 - mn0);
        float a1 = __expf(mrun1 - mn1);
        mrun0 = mn0; mrun1 = mn1;

        float rs0 = 0.0f, rs1 = 0.0f;
#pragma unroll
        for (int j = 0; j < 8; j++) {
            sacc[j][0] = (sacc[j][0] < -1e29f) ? 0.0f : __expf(sacc[j][0] - mn0);
            sacc[j][1] = (sacc[j][1] < -1e29f) ? 0.0f : __expf(sacc[j][1] - mn0);
            sacc[j][2] = (sacc[j][2] < -1e29f) ? 0.0f : __expf(sacc[j][2] - mn1);
            sacc[j][3] = (sacc[j][3] < -1e29f) ? 0.0f : __expf(sacc[j][3] - mn1);
            rs0 += sacc[j][0] + sacc[j][1];
            rs1 += sacc[j][2] + sacc[j][3];
        }
        rs0 += __shfl_xor_sync(0xffffffffu, rs0, 1);
        rs0 += __shfl_xor_sync(0xffffffffu, rs0, 2);
        rs1 += __shfl_xor_sync(0xffffffffu, rs1, 1);
        rs1 += __shfl_xor_sync(0xffffffffu, rs1, 2);
        lrun0 = lrun0 * a0 + rs0;
        lrun1 = lrun1 * a1 + rs1;

#pragma unroll
        for (int e = 0; e < 4; e++) {
            oacc[e][0] *= a0; oacc[e][1] *= a0;
            oacc[e][2] *= a1; oacc[e][3] *= a1;
        }

#pragma unroll
        for (int t = 0; t < 4; t++) {
            const int j0 = 2 * t, j1 = 2 * t + 1;
            unsigned ah[4], al[4];
            {
                unsigned h0 = packbf2(sacc[j0][0], sacc[j0][1]);
                unsigned h1 = packbf2(sacc[j0][2], sacc[j0][3]);
                unsigned h2 = packbf2(sacc[j1][0], sacc[j1][1]);
                unsigned h3 = packbf2(sacc[j1][2], sacc[j1][3]);
                ah[0] = h0; ah[1] = h1; ah[2] = h2; ah[3] = h3;
                float2 f0 = unpackbf2(h0), f1 = unpackbf2(h1);
                float2 f2 = unpackbf2(h2), f3 = unpackbf2(h3);
                al[0] = packbf2(sacc[j0][0] - f0.x, sacc[j0][1] - f0.y);
                al[1] = packbf2(sacc[j0][2] - f1.x, sacc[j0][3] - f1.y);
                al[2] = packbf2(sacc[j1][0] - f2.x, sacc[j1][1] - f2.y);
                al[3] = packbf2(sacc[j1][2] - f3.x, sacc[j1][3] - f3.y);
            }
            const int rowv = 16 * t + ((lane >> 3) & 1) * 8 + (lane & 7);
#pragma unroll
            for (int ep = 0; ep < 4; ep += 2) {
                unsigned cch = ep + (lane >> 4);
                unsigned vaddr = vsb + rowv * 128 + ((cch ^ (rowv & 7)) << 4);
                unsigned v0, v1, v2, v3;
                LDSM_X4T(v0, v1, v2, v3, vaddr);
                MMA16816(oacc[ep], ah, v0, v1);
                MMA16816(oacc[ep], al, v0, v1);
                MMA16816(oacc[ep + 1], ah, v2, v3);
                MMA16816(oacc[ep + 1], al, v2, v3);
                unsigned ccl = 4 + ep + (lane >> 4);
                unsigned laddr = vsb + rowv * 128 + ((ccl ^ (rowv & 7)) << 4);
                unsigned u0, u1, u2, u3;
                LDSM_X4T(u0, u1, u2, u3, laddr);
                MMA16816(oacc[ep], ah, u0, u1);
                MMA16816(oacc[ep + 1], ah, u2, u3);
            }
        }
        __syncthreads();   // compute done before stage reuse (iter kt+2 load)
    }

    const float inv0 = 1.0f / lrun0;
    const float inv1 = 1.0f / lrun1;
    const int n0 = qbase + m0 + gr;
#pragma unroll
    for (int e = 0; e < 4; e++) {
        int col = h * 32 + 8 * e + 2 * gc;
        split_pair(oabf + ((size_t)(n0 * BATCH + b)) * 512 + col, 256,
                   oacc[e][0] * inv0, oacc[e][1] * inv0);
        split_pair(oabf + ((size_t)((n0 + 8) * BATCH + b)) * 512 + col, 256,
                   oacc[e][2] * inv1, oacc[e][3] * inv1);
    }
}

// ---------------------------------------------------------------------------
// PE denominator table + fused embed+split
// ---------------------------------------------------------------------------
__global__ void pe_table_kernel(float* den) {
    int k = threadIdx.x;
    float e = (float)(2 * (k >> 1)) / 256.0f;
    den[k] = (float)pow(10000.0, (double)e);
}

__global__ __launch_bounds__(256) void add_pe_split_kernel(
    const float* __restrict__ nodes, const float* __restrict__ den,
    __nv_bfloat16* __restrict__ abf)
{
    int idx = blockIdx.x * 256 + threadIdx.x;   // NROWS*256
    int n = idx >> 11;
    int k = idx & 255;
    float ang = (float)n / den[k];
    double sv = (k & 1) ? cos((double)ang) : sin((double)ang);
    float w = nodes[idx] + (float)sv;
    __nv_bfloat16 hi = __float2bfloat16(w);
    float lo = w - __bfloat162float(hi);
    int m = idx >> 8;
    abf[(size_t)m * 512 + k] = hi;
    abf[(size_t)m * 512 + 256 + k] = __float2bfloat16(lo);
}

// ---------------------------------------------------------------------------
// LayerNorm (+residual) fused with hi|lo split output
// ---------------------------------------------------------------------------
__global__ __launch_bounds__(256) void ln_split_kernel(
    const float* __restrict__ y, const float* __restrict__ res,
    const float* __restrict__ g, const float* __restrict__ bt,
    float* __restrict__ xout, __nv_bfloat16* __restrict__ abf)
{
    __shared__ float red[8];
    const int r = blockIdx.x;
    const int c = threadIdx.x;

    float v = y[(size_t)r * HIDW + c];
    if (res) v += res[(size_t)r * HIDW + c];

    float s = v;
#pragma unroll
    for (int off = 16; off; off >>= 1) s += __shfl_xor_sync(0xffffffffu, s, off);
    if ((c & 31) == 0) red[c >> 5] = s;
    __syncthreads();
    float tot = 0.0f;
#pragma unroll
    for (int i = 0; i < 8; i++) tot += red[i];
    float mu = tot * (1.0f / HIDW);

    float d = v - mu;
    float s2 = d * d;
#pragma unroll
    for (int off = 16; off; off >>= 1) s2 += __shfl_xor_sync(0xffffffffu, s2, off);
    __syncthreads();
    if ((c & 31) == 0) red[c >> 5] = s2;
    __syncthreads();
    float tv = 0.0f;
#pragma unroll
    for (int i = 0; i < 8; i++) tv += red[i];
    float var = tv * (1.0f / HIDW);

    float o = d * rsqrtf(var + LEPS) * g[c] + bt[c];
    xout[(size_t)r * HIDW + c] = o;
    __nv_bfloat16 hi = __float2bfloat16(o);
    abf[(size_t)r * 512 + c] = hi;
    abf[(size_t)r * 512 + 256 + c] = __float2bfloat16(o - __bfloat162float(hi));
}

// ---------------------------------------------------------------------------
// Final batch-norm over B=8 at position n=0
// ---------------------------------------------------------------------------
__global__ __launch_bounds__(256) void bn_final_kernel(
    const float* __restrict__ x, const float* __restrict__ g,
    const float* __restrict__ bt, float* __restrict__ out)
{
    int c = threadIdx.x;
    float v[BATCH];
    float mu = 0.0f;
#pragma unroll
    for (int b = 0; b < BATCH; b++) {
        v[b] = x[(size_t)b * HIDW + c];
        mu += v[b];
    }
    mu *= (1.0f / BATCH);
    float var = 0.0f;
#pragma unroll
    for (int b = 0; b < BATCH; b++) {
        float d = v[b] - mu;
        var += d * d;
    }
    var *= (1.0f / BATCH);
    float rs = rsqrtf(var + LEPS);
#pragma unroll
    for (int b = 0; b < BATCH; b++)
        out[b * HIDW + c] = (v[b] - mu) * rs * g[c] + bt[c];
}

// ---------------------------------------------------------------------------
// Launch
// ---------------------------------------------------------------------------
#define SMEM128 (2 * (128 * 128 + 16384))   // 65536
#define SMEM64  (2 * (64 * 128 + 16384))    // 49152

extern "C" void kernel_launch(void* const* d_in, const int* in_sizes, int n_in,
                              void* d_out, int out_size)
{
    const float* nodes   = (const float*)d_in[0];
    const int*   dist    = (const int*)  d_in[1];
    const float* W_in    = (const float*)d_in[2];
    const float* b_in    = (const float*)d_in[3];
    const float* ln_in_g = (const float*)d_in[4];
    const float* ln_in_b = (const float*)d_in[5];
    const float* Wqkv    = (const float*)d_in[6];
    const float* bqkv    = (const float*)d_in[7];
    const float* Wo      = (const float*)d_in[8];
    const float* bo      = (const float*)d_in[9];
    const float* ln1_g   = (const float*)d_in[10];
    const float* ln1_b   = (const float*)d_in[11];
    const float* W1      = (const float*)d_in[12];
    const float* b1      = (const float*)d_in[13];
    const float* W2      = (const float*)d_in[14];
    const float* b2      = (const float*)d_in[15];
    const float* ln2_g   = (const float*)d_in[16];
    const float* ln2_b   = (const float*)d_in[17];
    const float* bn_g    = (const float*)d_in[18];
    const float* bn_b    = (const float*)d_in[19];
    float* outp = (float*)d_out;

    float *x, *y, *den;
    __nv_bfloat16 *abf, *abf2, *wtall, *qb, *kb, *vb;
    unsigned *m1, *m2;
    cudaGetSymbolAddress((void**)&x,     g_x);
    cudaGetSymbolAddress((void**)&y,     g_y);
    cudaGetSymbolAddress((void**)&den,   g_den);
    cudaGetSymbolAddress((void**)&abf,   g_abf);
    cudaGetSymbolAddress((void**)&abf2,  g_abf2);
    cudaGetSymbolAddress((void**)&wtall, g_wtall);
    cudaGetSymbolAddress((void**)&qb,    g_qb);
    cudaGetSymbolAddress((void**)&kb,    g_kb);
    cudaGetSymbolAddress((void**)&vb,    g_vb);
    cudaGetSymbolAddress((void**)&m1,    g_m1);
    cudaGetSymbolAddress((void**)&m2,    g_m2);

    cudaFuncSetAttribute(hmma_gemm_t<128>,
                         cudaFuncAttributeMaxDynamicSharedMemorySize, SMEM128);
    cudaFuncSetAttribute(hmma_gemm_t<64>,
                         cudaFuncAttributeMaxDynamicSharedMemorySize, SMEM64);

    // weight layout in g_wtall (bf16 offsets)
    const long offWin  = 0;
    const long offQKV[2] = {131072, 1179648};
    const long offWo [2] = {524288, 1572864};
    const long offW1 [2] = {655360, 1703936};
    const long offW2 [2] = {917504, 1966080};

    // 0. one-shot weight conversion
    ConvJobs J;
    J.src[0] = W_in;            J.dstOff[0] = offWin;    J.K[0] = 256; J.Nc[0] = 256;
    J.src[1] = Wqkv;            J.dstOff[1] = offQKV[0]; J.K[1] = 256; J.Nc[1] = 768;
    J.src[2] = Wo;              J.dstOff[2] = offWo[0];  J.K[2] = 256; J.Nc[2] = 256;
    J.src[3] = W1;              J.dstOff[3] = offW1[0];  J.K[3] = 256; J.Nc[3] = 512;
    J.src[4] = W2;              J.dstOff[4] = offW2[0];  J.K[4] = 512; J.Nc[4] = 256;
    J.src[5] = Wqkv + 196608;   J.dstOff[5] = offQKV[1]; J.K[5] = 256; J.Nc[5] = 768;
    J.src[6] = Wo + 65536;      J.dstOff[6] = offWo[1];  J.K[6] = 256; J.Nc[6] = 256;
    J.src[7] = W1 + 131072;     J.dstOff[7] = offW1[1];  J.K[7] = 256; J.Nc[7] = 512;
    J.src[8] = W2 + 131072;     J.dstOff[8] = offW2[1];  J.K[8] = 512; J.Nc[8] = 256;
    J.start[0] = 0;      J.start[1] = 65536;  J.start[2] = 262144;
    J.start[3] = 327680; J.start[4] = 458752; J.start[5] = 589824;
    J.start[6] = 786432; J.start[7] = 851968; J.start[8] = 983040;
    J.start[9] = 1114112;
    convW_all_kernel<<<1114112 / 256, 256>>>(J, wtall);

    // masks + PE embed
    mask_kernel<<<(BATCH * NTOK * NTOK / 32) / 8, 256>>>(dist, m1, m2);
    pe_table_kernel<<<1, 256>>>(den);
    add_pe_split_kernel<<<(NROWS * DIN) / 256, 256>>>(nodes, den, abf);

    // input projection + LN(+split)
    hmma_gemm_t<64><<<dim3(2, 128), 256, SMEM64>>>(
        abf, wtall + offWin, b_in, y, nullptr, nullptr, nullptr, nullptr,
        256, 256, 0);
    ln_split_kernel<<<NROWS, 256>>>(y, nullptr, ln_in_g, ln_in_b, x, abf);

    // transformer layers
    for (int l = 0; l < 2; l++) {
        hmma_gemm_t<128><<<dim3(6, 64), 256, SMEM128>>>(
            abf, wtall + offQKV[l], bqkv + l * 768, nullptr, nullptr,
            qb, kb, vb, 256, 768, 2);

        attn_mma_kernel<<<dim3(NTOK / QTA, BATCH * NHEAD), 256>>>(
            qb, kb, vb, m1, m2, abf);

        hmma_gemm_t<64><<<dim3(2, 128), 256, SMEM64>>>(
            abf, wtall + offWo[l], bo + l * 256, y, nullptr,
            nullptr, nullptr, nullptr, 256, 256, 0);
        ln_split_kernel<<<NROWS, 256>>>(y, x, ln1_g + l * 256, ln1_b + l * 256,
                                        x, abf);

        hmma_gemm_t<128><<<dim3(4, 64), 256, SMEM128>>>(
            abf, wtall + offW1[l], b1 + l * 512, nullptr, abf2,
            nullptr, nullptr, nullptr, 256, 512, 1);
        hmma_gemm_t<64><<<dim3(2, 128), 256, SMEM64>>>(
            abf2, wtall + offW2[l], b2 + l * 256, y, nullptr,
            nullptr, nullptr, nullptr, 512, 256, 0);
        ln_split_kernel<<<NROWS, 256>>>(y, x, ln2_g + l * 256, ln2_b + l * 256,
                                        x, abf);
    }

    // final batch-norm of x[0]
    bn_final_kernel<<<1, 256>>>(x, bn_g, bn_b, outp);
}

// round 17
// speedup vs baseline: 2.4319x; 1.3052x over previous
#include <cuda_runtime.h>
#include <cuda_bf16.h>
#include <math.h>

// ---------------------------------------------------------------------------
// Problem constants
// ---------------------------------------------------------------------------
#define NTOK   1024
#define BATCH  8
#define DIN    256
#define HIDW   256
#define NROWS  (NTOK * BATCH)      // 8192
#define NHEAD  8
#define DH     32
#define LEPS   1e-5f

// ---------------------------------------------------------------------------
// Scratch (static device globals — no allocation allowed)
// ---------------------------------------------------------------------------
__device__ __align__(16) float g_x  [NROWS * HIDW];
__device__ __align__(16) float g_y  [NROWS * HIDW];
__device__ float g_den[DIN];
__device__ __align__(16) float g_pe [NTOK * DIN];             // PE table
__device__ __align__(16) __nv_bfloat16 g_abf [NROWS * 512];   // A hi|lo, K=256 layout
__device__ __align__(16) __nv_bfloat16 g_abf2[NROWS * 1024];  // FFN hidden hi|lo, K=512
__device__ __align__(16) __nv_bfloat16 g_wtall[2228224];      // ALL W^T hi|lo
// head-major bf16 hi|lo QKV: [B*H][N][64] (hi d 0..31, lo 32..63)
__device__ __align__(16) __nv_bfloat16 g_qb[64 * NTOK * 64];
__device__ __align__(16) __nv_bfloat16 g_kb[64 * NTOK * 64];
__device__ __align__(16) __nv_bfloat16 g_vb[64 * NTOK * 64];
// bit masks: word bit k = allowed(col)
__device__ unsigned g_m1[BATCH * NTOK * (NTOK / 32)];   // dist == 1
__device__ unsigned g_m2[BATCH * NTOK * (NTOK / 32)];   // dist >= 1

// ---------------------------------------------------------------------------
// Common helpers
// ---------------------------------------------------------------------------
__device__ __forceinline__ unsigned smem_u32(const void* p) {
    unsigned a;
    asm("{ .reg .u64 t; cvta.to.shared.u64 t, %1; cvt.u32.u64 %0, t; }"
        : "=r"(a) : "l"(p));
    return a;
}

#define LDSM_X4(r0, r1, r2, r3, addr) \
    asm volatile("ldmatrix.sync.aligned.m8n8.x4.shared.b16 {%0,%1,%2,%3}, [%4];" \
                 : "=r"(r0), "=r"(r1), "=r"(r2), "=r"(r3) : "r"(addr))

#define LDSM_X4T(r0, r1, r2, r3, addr) \
    asm volatile("ldmatrix.sync.aligned.m8n8.x4.trans.shared.b16 {%0,%1,%2,%3}, [%4];" \
                 : "=r"(r0), "=r"(r1), "=r"(r2), "=r"(r3) : "r"(addr))

#define MMA16816(d, a, b0v, b1v) \
    asm volatile("mma.sync.aligned.m16n8k16.row.col.f32.bf16.bf16.f32 " \
                 "{%0,%1,%2,%3}, {%4,%5,%6,%7}, {%8,%9}, {%0,%1,%2,%3};" \
                 : "+f"((d)[0]), "+f"((d)[1]), "+f"((d)[2]), "+f"((d)[3]) \
                 : "r"((a)[0]), "r"((a)[1]), "r"((a)[2]), "r"((a)[3]), \
                   "r"(b0v), "r"(b1v))

#define CP_ASYNC16(dst, src) \
    asm volatile("cp.async.cg.shared.global [%0], [%1], 16;" \
                 :: "r"(dst), "l"(src))
#define CP_COMMIT() asm volatile("cp.async.commit_group;" ::: "memory")
#define CP_WAIT1()  asm volatile("cp.async.wait_group 1;" ::: "memory")
#define CP_WAIT0()  asm volatile("cp.async.wait_group 0;" ::: "memory")

__device__ __forceinline__ unsigned packbf2(float x, float y) {
    __nv_bfloat162 t = __floats2bfloat162_rn(x, y);
    return *reinterpret_cast<unsigned*>(&t);
}
__device__ __forceinline__ float2 unpackbf2(unsigned u) {
    __nv_bfloat162 t = *reinterpret_cast<__nv_bfloat162*>(&u);
    return make_float2(__bfloat162float(t.x), __bfloat162float(t.y));
}
__device__ __forceinline__ void split_pair(__nv_bfloat16* p, int ofs,
                                           float x0, float x1) {
    unsigned hp = packbf2(x0, x1);
    float2 hf = unpackbf2(hp);
    unsigned lp = packbf2(x0 - hf.x, x1 - hf.y);
    *(unsigned*)p = hp;
    *(unsigned*)(p + ofs) = lp;
}

// ---------------------------------------------------------------------------
// One-shot conversion of ALL weights: W [K,Nc] -> Wt [Nc,2K] bf16 hi|lo
// ---------------------------------------------------------------------------
struct ConvJobs {
    const float* src[9];
    long dstOff[9];
    int K[9];
    int Nc[9];
    int start[10];
};

__global__ __launch_bounds__(256) void convW_all_kernel(
    ConvJobs J, __nv_bfloat16* __restrict__ d)
{
    int idx = blockIdx.x * 256 + threadIdx.x;
    int r = 0;
#pragma unroll
    for (int i = 1; i < 9; i++) if (idx >= J.start[i]) r = i;
    int li = idx - J.start[r];
    int K = J.K[r], Nc = J.Nc[r];
    int k = li / Nc, n = li - k * Nc;
    float w = J.src[r][li];
    __nv_bfloat16 hi = __float2bfloat16(w);
    float lo = w - __bfloat162float(hi);
    __nv_bfloat16* dst = d + J.dstOff[r];
    dst[(size_t)n * 2 * K + k] = hi;
    dst[(size_t)n * 2 * K + K + k] = __float2bfloat16(lo);
}

// dist -> bit masks (one warp per 32 cols)
__global__ __launch_bounds__(256) void mask_kernel(
    const int* __restrict__ dist, unsigned* __restrict__ m1,
    unsigned* __restrict__ m2)
{
    int gw = (blockIdx.x * 256 + threadIdx.x) >> 5;
    int lane = threadIdx.x & 31;
    int d = dist[(size_t)gw * 32 + lane];
    unsigned b1 = __ballot_sync(0xffffffffu, d == 1);
    unsigned b2 = __ballot_sync(0xffffffffu, d >= 1);
    if (lane == 0) { m1[gw] = b1; m2[gw] = b2; }
}

// ---------------------------------------------------------------------------
// HMMA bf16 GEMM, 2-stage cp.async pipeline, templated on BM (128 or 64).
// ---------------------------------------------------------------------------
template<int BM>
__global__ __launch_bounds__(256) void hmma_gemm_t(
    const __nv_bfloat16* __restrict__ A2, const __nv_bfloat16* __restrict__ Wt,
    const float* __restrict__ bias, float* __restrict__ C,
    __nv_bfloat16* __restrict__ osplit,
    __nv_bfloat16* __restrict__ qb, __nv_bfloat16* __restrict__ kb,
    __nv_bfloat16* __restrict__ vb,
    int K, int Nc, int mode)
{
    extern __shared__ __align__(16) char sm[];

    constexpr int NW_M = BM / 32;          // 4 or 2
    constexpr int WN = 128 / (8 / NW_M);   // 64 or 32
    constexpr int NFRAG = WN / 8;          // 8 or 4
    constexpr int SB = BM * 128 + 16384;   // stage bytes (A + B)

    const int tid = threadIdx.x;
    const int wid = tid >> 5;
    const int lane = tid & 31;
    const int wm0 = (wid % NW_M) * 32;
    const int wn0 = (wid / NW_M) * WN;
    const int mBase = blockIdx.y * BM;
    const int nBase = blockIdx.x * 128;
    const int stride2K = 2 * K;
    const int T = (3 * K) / 64;

    const unsigned smb = smem_u32(sm);

    float acc[2][NFRAG][4];
#pragma unroll
    for (int am = 0; am < 2; am++)
#pragma unroll
        for (int bn = 0; bn < NFRAG; bn++)
#pragma unroll
            for (int c = 0; c < 4; c++) acc[am][bn][c] = 0.0f;

    const int a_row_in = lane & 15;
    const int a_blk = lane >> 4;
    const int b_q = lane >> 3;
    const int b_r = lane & 7;

    auto load_tile = [&](int t, int stage) {
        const int kc64 = t * 64;
        const int aoff = (kc64 < 2 * K) ? kc64 : kc64 - 2 * K;
        const int woff = (kc64 < K) ? kc64 : kc64 - K;
        const unsigned ab = smb + stage * SB;
        const unsigned bbs = ab + BM * 128;
#pragma unroll
        for (int i = 0; i < BM / 32; i++) {
            int idx = i * 256 + tid;
            int row = idx >> 3, ch = idx & 7;
            unsigned sw = row * 128 + ((ch ^ (row & 7)) << 4);
            CP_ASYNC16(ab + sw, A2 + (size_t)(mBase + row) * stride2K + aoff + ch * 8);
        }
#pragma unroll
        for (int i = 0; i < 4; i++) {
            int idx = i * 256 + tid;
            int row = idx >> 3, ch = idx & 7;
            unsigned sw = row * 128 + ((ch ^ (row & 7)) << 4);
            CP_ASYNC16(bbs + sw, Wt + (size_t)(nBase + row) * stride2K + woff + ch * 8);
        }
    };

    load_tile(0, 0);
    CP_COMMIT();

    for (int t = 0; t < T; t++) {
        if (t + 1 < T) {
            load_tile(t + 1, (t + 1) & 1);
            CP_COMMIT();
            CP_WAIT1();
        } else {
            CP_WAIT0();
        }
        __syncthreads();

        const unsigned asb = smb + (t & 1) * SB;
        const unsigned bsb = asb + BM * 128;

#pragma unroll
        for (int ks = 0; ks < 4; ks++) {
            const int kc = ks * 2;
            unsigned af[2][4];
#pragma unroll
            for (int am = 0; am < 2; am++) {
                int row = wm0 + am * 16 + a_row_in;
                unsigned addr = asb + row * 128 + (((kc + a_blk) ^ (row & 7)) << 4);
                LDSM_X4(af[am][0], af[am][1], af[am][2], af[am][3], addr);
            }
            unsigned bf[NFRAG / 2][4];
#pragma unroll
            for (int bn2 = 0; bn2 < NFRAG / 2; bn2++) {
                int n_row = wn0 + bn2 * 16 + ((b_q >> 1) << 3) + b_r;
                unsigned addr = bsb + n_row * 128 + (((kc + (b_q & 1)) ^ (n_row & 7)) << 4);
                LDSM_X4(bf[bn2][0], bf[bn2][1], bf[bn2][2], bf[bn2][3], addr);
            }
#pragma unroll
            for (int am = 0; am < 2; am++)
#pragma unroll
                for (int bn2 = 0; bn2 < NFRAG / 2; bn2++) {
                    MMA16816(acc[am][bn2 * 2 + 0], af[am], bf[bn2][0], bf[bn2][1]);
                    MMA16816(acc[am][bn2 * 2 + 1], af[am], bf[bn2][2], bf[bn2][3]);
                }
        }
        __syncthreads();
    }

    // ---- epilogue ----
    const int gr = lane >> 2;
    const int gc2 = (lane & 3) * 2;
#pragma unroll
    for (int am = 0; am < 2; am++) {
#pragma unroll
        for (int bn = 0; bn < NFRAG; bn++) {
            int col = nBase + wn0 + bn * 8 + gc2;
            float b0 = bias[col], b1 = bias[col + 1];
            int row0 = mBase + wm0 + am * 16 + gr;
            float v00 = acc[am][bn][0] + b0, v01 = acc[am][bn][1] + b1;
            float v10 = acc[am][bn][2] + b0, v11 = acc[am][bn][3] + b1;
            if (mode == 0) {
                *(float2*)(C + (size_t)row0 * Nc + col) = make_float2(v00, v01);
                *(float2*)(C + (size_t)(row0 + 8) * Nc + col) = make_float2(v10, v11);
            } else if (mode == 1) {
                v00 = fmaxf(v00, 0.0f); v01 = fmaxf(v01, 0.0f);
                v10 = fmaxf(v10, 0.0f); v11 = fmaxf(v11, 0.0f);
                split_pair(osplit + (size_t)row0 * 1024 + col, 512, v00, v01);
                split_pair(osplit + (size_t)(row0 + 8) * 1024 + col, 512, v10, v11);
            } else {
                int sec = col >> 8;
                int h = (col >> 5) & 7;
                int d = col & 31;
                __nv_bfloat16* bp = (sec == 0) ? qb : (sec == 1) ? kb : vb;
                int n0 = row0 >> 3, bb0 = row0 & 7;
                split_pair(bp + ((size_t)((bb0 * 8 + h) * NTOK + n0)) * 64 + d,
                           32, v00, v01);
                int n1 = (row0 + 8) >> 3, bb1 = (row0 + 8) & 7;
                split_pair(bp + ((size_t)((bb1 * 8 + h) * NTOK + n1)) * 64 + d,
                           32, v10, v11);
            }
        }
    }
}

// ---------------------------------------------------------------------------
// HMMA flash attention with 2-stage cp.async K/V pipeline (R16, passing).
// ---------------------------------------------------------------------------
#define QTA 128
#define KTA 64

__global__ __launch_bounds__(256) void attn_mma_kernel(
    const __nv_bfloat16* __restrict__ Qb, const __nv_bfloat16* __restrict__ Kb,
    const __nv_bfloat16* __restrict__ Vb,
    const unsigned* __restrict__ m1, const unsigned* __restrict__ m2,
    __nv_bfloat16* __restrict__ oabf)
{
    __shared__ __align__(16) char Qs[128 * 128];
    __shared__ __align__(16) char KV[2][16384];   // per stage: K 8KB | V 8KB

    const int tid = threadIdx.x;
    const int wid = tid >> 5;
    const int lane = tid & 31;
    const int bh = blockIdx.y;
    const int b = bh >> 3;
    const int h = bh & 7;
    const int qbase = blockIdx.x * QTA;
    const int m0 = wid * 16;
    const int gr = lane >> 2;
    const int gc = lane & 3;
    const int mtype = (h < 2) ? 1 : (h < 6) ? 2 : 0;
    const unsigned* mwsel = (mtype == 1) ? m1 : m2;
    const float SCALE = 0.17677669529663687f;   // 1/sqrt(32)

    const unsigned qsb = smem_u32(Qs);
    const unsigned kvb = smem_u32(KV);

    const __nv_bfloat16* Qg = Qb + ((size_t)bh * NTOK + qbase) * 64;
#pragma unroll
    for (int i = 0; i < 4; i++) {
        int idx = i * 256 + tid;
        int row = idx >> 3, ch = idx & 7;
        int4 v = *(const int4*)(Qg + row * 64 + ch * 8);
        *(int4*)(Qs + row * 128 + ((ch ^ (row & 7)) << 4)) = v;
    }

    auto loadKV = [&](int kt, int stg) {
        const __nv_bfloat16* Kg = Kb + ((size_t)bh * NTOK + kt * KTA) * 64;
        const __nv_bfloat16* Vg = Vb + ((size_t)bh * NTOK + kt * KTA) * 64;
        const unsigned kd = kvb + stg * 16384;
        const unsigned vd = kd + 8192;
#pragma unroll
        for (int i = 0; i < 2; i++) {
            int idx = i * 256 + tid;
            int row = idx >> 3, ch = idx & 7;
            unsigned sw = row * 128 + ((ch ^ (row & 7)) << 4);
            CP_ASYNC16(kd + sw, Kg + row * 64 + ch * 8);
            CP_ASYNC16(vd + sw, Vg + row * 64 + ch * 8);
        }
    };

    float oacc[4][4];
#pragma unroll
    for (int e = 0; e < 4; e++)
#pragma unroll
        for (int c = 0; c < 4; c++) oacc[e][c] = 0.0f;
    float mrun0 = -1e30f, mrun1 = -1e30f, lrun0 = 0.0f, lrun1 = 0.0f;

    const int rowa = m0 + (lane & 15);
    const int ablk = lane >> 4;

    loadKV(0, 0);
    CP_COMMIT();

    for (int kt = 0; kt < NTOK / KTA; kt++) {
        const int kb = kt * KTA;
        if (kt + 1 < NTOK / KTA) {
            loadKV(kt + 1, (kt + 1) & 1);
            CP_COMMIT();
            CP_WAIT1();
        } else {
            CP_WAIT0();
        }
        __syncthreads();

        const unsigned ksb = kvb + (kt & 1) * 16384;
        const unsigned vsb = ksb + 8192;

        unsigned wr[2][2];
        if (mtype) {
#pragma unroll
            for (int r = 0; r < 2; r++) {
                int row = qbase + m0 + gr + r * 8;
                const unsigned* p = mwsel + ((size_t)b * NTOK + row) * (NTOK / 32) + (kb >> 5);
                wr[r][0] = p[0];
                wr[r][1] = p[1];
            }
        }

        float sacc[8][4];
#pragma unroll
        for (int j = 0; j < 8; j++)
#pragma unroll
            for (int c = 0; c < 4; c++) sacc[j][c] = 0.0f;

        const int steps_a[6] = {0, 2, 4, 6, 0, 2};
        const int steps_b[6] = {0, 2, 0, 2, 4, 6};
#pragma unroll
        for (int s = 0; s < 6; s++) {
            unsigned aq[4];
            unsigned aaddr = qsb + rowa * 128 + (((steps_a[s] + ablk) ^ (rowa & 7)) << 4);
            LDSM_X4(aq[0], aq[1], aq[2], aq[3], aaddr);
            const int cc = steps_b[s] + ((lane >> 3) & 1);
#pragma unroll
            for (int j = 0; j < 8; j += 2) {
                int rowk = 8 * j + ((lane >> 4) << 3) + (lane & 7);
                unsigned kaddr = ksb + rowk * 128 + ((cc ^ (rowk & 7)) << 4);
                unsigned kf0, kf1, kf2, kf3;
                LDSM_X4(kf0, kf1, kf2, kf3, kaddr);
                MMA16816(sacc[j], aq, kf0, kf1);
                MMA16816(sacc[j + 1], aq, kf2, kf3);
            }
        }

#pragma unroll
        for (int j = 0; j < 8; j++) {
            if (mtype) {
                int col0 = 8 * j + 2 * gc;
                int wi = col0 >> 5, sh = col0 & 31;
                sacc[j][0] = ((wr[0][wi] >> sh) & 1)       ? sacc[j][0] * SCALE : -1e30f;
                sacc[j][1] = ((wr[0][wi] >> (sh + 1)) & 1) ? sacc[j][1] * SCALE : -1e30f;
                sacc[j][2] = ((wr[1][wi] >> sh) & 1)       ? sacc[j][2] * SCALE : -1e30f;
                sacc[j][3] = ((wr[1][wi] >> (sh + 1)) & 1) ? sacc[j][3] * SCALE : -1e30f;
            } else {
                sacc[j][0] *= SCALE; sacc[j][1] *= SCALE;
                sacc[j][2] *= SCALE; sacc[j][3] *= SCALE;
            }
        }

        float tm0 = -1e30f, tm1 = -1e30f;
#pragma unroll
        for (int j = 0; j < 8; j++) {
            tm0 = fmaxf(tm0, fmaxf(sacc[j][0], sacc[j][1]));
            tm1 = fmaxf(tm1, fmaxf(sacc[j][2], sacc[j][3]));
        }
        tm0 = fmaxf(tm0, __shfl_xor_sync(0xffffffffu, tm0, 1));
        tm0 = fmaxf(tm0, __shfl_xor_sync(0xffffffffu, tm0, 2));
        tm1 = fmaxf(tm1, __shfl_xor_sync(0xffffffffu, tm1, 1));
        tm1 = fmaxf(tm1, __shfl_xor_sync(0xffffffffu, tm1, 2));

        float mn0 = fmaxf(mrun0, tm0);
        float mn1 = fmaxf(mrun1, tm1);
        float a0 = __expf(mrun0 - mn0);
        float a1 = __expf(mrun1 - mn1);
        mrun0 = mn0; mrun1 = mn1;

        float rs0 = 0.0f, rs1 = 0.0f;
#pragma unroll
        for (int j = 0; j < 8; j++) {
            sacc[j][0] = (sacc[j][0] < -1e29f) ? 0.0f : __expf(sacc[j][0] - mn0);
            sacc[j][1] = (sacc[j][1] < -1e29f) ? 0.0f : __expf(sacc[j][1] - mn0);
            sacc[j][2] = (sacc[j][2] < -1e29f) ? 0.0f : __expf(sacc[j][2] - mn1);
            sacc[j][3] = (sacc[j][3] < -1e29f) ? 0.0f : __expf(sacc[j][3] - mn1);
            rs0 += sacc[j][0] + sacc[j][1];
            rs1 += sacc[j][2] + sacc[j][3];
        }
        rs0 += __shfl_xor_sync(0xffffffffu, rs0, 1);
        rs0 += __shfl_xor_sync(0xffffffffu, rs0, 2);
        rs1 += __shfl_xor_sync(0xffffffffu, rs1, 1);
        rs1 += __shfl_xor_sync(0xffffffffu, rs1, 2);
        lrun0 = lrun0 * a0 + rs0;
        lrun1 = lrun1 * a1 + rs1;

#pragma unroll
        for (int e = 0; e < 4; e++) {
            oacc[e][0] *= a0; oacc[e][1] *= a0;
            oacc[e][2] *= a1; oacc[e][3] *= a1;
        }

#pragma unroll
        for (int t = 0; t < 4; t++) {
            const int j0 = 2 * t, j1 = 2 * t + 1;
            unsigned ah[4], al[4];
            {
                unsigned h0 = packbf2(sacc[j0][0], sacc[j0][1]);
                unsigned h1 = packbf2(sacc[j0][2], sacc[j0][3]);
                unsigned h2 = packbf2(sacc[j1][0], sacc[j1][1]);
                unsigned h3 = packbf2(sacc[j1][2], sacc[j1][3]);
                ah[0] = h0; ah[1] = h1; ah[2] = h2; ah[3] = h3;
                float2 f0 = unpackbf2(h0), f1 = unpackbf2(h1);
                float2 f2 = unpackbf2(h2), f3 = unpackbf2(h3);
                al[0] = packbf2(sacc[j0][0] - f0.x, sacc[j0][1] - f0.y);
                al[1] = packbf2(sacc[j0][2] - f1.x, sacc[j0][3] - f1.y);
                al[2] = packbf2(sacc[j1][0] - f2.x, sacc[j1][1] - f2.y);
                al[3] = packbf2(sacc[j1][2] - f3.x, sacc[j1][3] - f3.y);
            }
            const int rowv = 16 * t + ((lane >> 3) & 1) * 8 + (lane & 7);
#pragma unroll
            for (int ep = 0; ep < 4; ep += 2) {
                unsigned cch = ep + (lane >> 4);
                unsigned vaddr = vsb + rowv * 128 + ((cch ^ (rowv & 7)) << 4);
                unsigned v0, v1, v2, v3;
                LDSM_X4T(v0, v1, v2, v3, vaddr);
                MMA16816(oacc[ep], ah, v0, v1);
                MMA16816(oacc[ep], al, v0, v1);
                MMA16816(oacc[ep + 1], ah, v2, v3);
                MMA16816(oacc[ep + 1], al, v2, v3);
                unsigned ccl = 4 + ep + (lane >> 4);
                unsigned laddr = vsb + rowv * 128 + ((ccl ^ (rowv & 7)) << 4);
                unsigned u0, u1, u2, u3;
                LDSM_X4T(u0, u1, u2, u3, laddr);
                MMA16816(oacc[ep], ah, u0, u1);
                MMA16816(oacc[ep + 1], ah, u2, u3);
            }
        }
        __syncthreads();
    }

    const float inv0 = 1.0f / lrun0;
    const float inv1 = 1.0f / lrun1;
    const int n0 = qbase + m0 + gr;
#pragma unroll
    for (int e = 0; e < 4; e++) {
        int col = h * 32 + 8 * e + 2 * gc;
        split_pair(oabf + ((size_t)(n0 * BATCH + b)) * 512 + col, 256,
                   oacc[e][0] * inv0, oacc[e][1] * inv0);
        split_pair(oabf + ((size_t)((n0 + 8) * BATCH + b)) * 512 + col, 256,
                   oacc[e][2] * inv1, oacc[e][3] * inv1);
    }
}

// ---------------------------------------------------------------------------
// PE: denominator table (fp64 pow, 256 elems), full table (fp32 sin/cos,
// 262K elems — batch-deduplicated), then fused add+split (memory-bound).
// ---------------------------------------------------------------------------
__global__ void pe_table_kernel(float* den) {
    int k = threadIdx.x;
    float e = (float)(2 * (k >> 1)) / 256.0f;
    den[k] = (float)pow(10000.0, (double)e);
}

__global__ __launch_bounds__(256) void pe_full_kernel(
    const float* __restrict__ den, float* __restrict__ pe)
{
    int idx = blockIdx.x * 256 + threadIdx.x;   // NTOK*DIN
    int n = idx >> 8;
    int k = idx & 255;
    float ang = (float)n / den[k];
    pe[idx] = (k & 1) ? cosf(ang) : sinf(ang);
}

__global__ __launch_bounds__(256) void add_pe_split_kernel(
    const float* __restrict__ nodes, const float* __restrict__ pe,
    __nv_bfloat16* __restrict__ abf)
{
    int idx = blockIdx.x * 256 + threadIdx.x;   // NROWS*256
    int k = idx & 255;
    int m = idx >> 8;                           // row = n*8+b
    float w = nodes[idx] + pe[((m >> 3) << 8) | k];
    __nv_bfloat16 hi = __float2bfloat16(w);
    abf[(size_t)m * 512 + k] = hi;
    abf[(size_t)m * 512 + 256 + k] = __float2bfloat16(w - __bfloat162float(hi));
}

// ---------------------------------------------------------------------------
// LayerNorm (+residual) fused with hi|lo split — one WARP per row, no
// __syncthreads. 8 warps/block, float4 loads, shfl-only reductions.
// ---------------------------------------------------------------------------
__global__ __launch_bounds__(256) void ln_split_kernel(
    const float* __restrict__ y, const float* __restrict__ res,
    const float* __restrict__ g, const float* __restrict__ bt,
    float* __restrict__ xout, __nv_bfloat16* __restrict__ abf)
{
    const int w = threadIdx.x >> 5;
    const int lane = threadIdx.x & 31;
    const int r = blockIdx.x * 8 + w;
    const int c0 = lane * 8;

    const float* yp = y + (size_t)r * HIDW + c0;
    float4 a0 = *(const float4*)yp;
    float4 a1 = *(const float4*)(yp + 4);
    if (res) {
        const float* rp = res + (size_t)r * HIDW + c0;
        float4 r0 = *(const float4*)rp;
        float4 r1 = *(const float4*)(rp + 4);
        a0.x += r0.x; a0.y += r0.y; a0.z += r0.z; a0.w += r0.w;
        a1.x += r1.x; a1.y += r1.y; a1.z += r1.z; a1.w += r1.w;
    }
    float v[8] = {a0.x, a0.y, a0.z, a0.w, a1.x, a1.y, a1.z, a1.w};

    float s = ((v[0] + v[1]) + (v[2] + v[3])) + ((v[4] + v[5]) + (v[6] + v[7]));
#pragma unroll
    for (int off = 16; off; off >>= 1) s += __shfl_xor_sync(0xffffffffu, s, off);
    float mu = s * (1.0f / HIDW);

    float d[8], s2 = 0.0f;
#pragma unroll
    for (int i = 0; i < 8; i++) { d[i] = v[i] - mu; s2 += d[i] * d[i]; }
#pragma unroll
    for (int off = 16; off; off >>= 1) s2 += __shfl_xor_sync(0xffffffffu, s2, off);
    float rstd = rsqrtf(s2 * (1.0f / HIDW) + LEPS);

    float4 g0 = *(const float4*)(g + c0);
    float4 g1 = *(const float4*)(g + c0 + 4);
    float4 b0 = *(const float4*)(bt + c0);
    float4 b1 = *(const float4*)(bt + c0 + 4);
    float gg[8] = {g0.x, g0.y, g0.z, g0.w, g1.x, g1.y, g1.z, g1.w};
    float bb[8] = {b0.x, b0.y, b0.z, b0.w, b1.x, b1.y, b1.z, b1.w};

    float o[8];
#pragma unroll
    for (int i = 0; i < 8; i++) o[i] = d[i] * rstd * gg[i] + bb[i];

    float* xp = xout + (size_t)r * HIDW + c0;
    *(float4*)xp = make_float4(o[0], o[1], o[2], o[3]);
    *(float4*)(xp + 4) = make_float4(o[4], o[5], o[6], o[7]);

    __nv_bfloat16* ap = abf + (size_t)r * 512 + c0;
#pragma unroll
    for (int i = 0; i < 8; i += 2) split_pair(ap + i, 256, o[i], o[i + 1]);
}

// ---------------------------------------------------------------------------
// Final batch-norm over B=8 at position n=0
// ---------------------------------------------------------------------------
__global__ __launch_bounds__(256) void bn_final_kernel(
    const float* __restrict__ x, const float* __restrict__ g,
    const float* __restrict__ bt, float* __restrict__ out)
{
    int c = threadIdx.x;
    float v[BATCH];
    float mu = 0.0f;
#pragma unroll
    for (int b = 0; b < BATCH; b++) {
        v[b] = x[(size_t)b * HIDW + c];
        mu += v[b];
    }
    mu *= (1.0f / BATCH);
    float var = 0.0f;
#pragma unroll
    for (int b = 0; b < BATCH; b++) {
        float d = v[b] - mu;
        var += d * d;
    }
    var *= (1.0f / BATCH);
    float rs = rsqrtf(var + LEPS);
#pragma unroll
    for (int b = 0; b < BATCH; b++)
        out[b * HIDW + c] = (v[b] - mu) * rs * g[c] + bt[c];
}

// ---------------------------------------------------------------------------
// Launch
// ---------------------------------------------------------------------------
#define SMEM128 (2 * (128 * 128 + 16384))   // 65536
#define SMEM64  (2 * (64 * 128 + 16384))    // 49152

extern "C" void kernel_launch(void* const* d_in, const int* in_sizes, int n_in,
                              void* d_out, int out_size)
{
    const float* nodes   = (const float*)d_in[0];
    const int*   dist    = (const int*)  d_in[1];
    const float* W_in    = (const float*)d_in[2];
    const float* b_in    = (const float*)d_in[3];
    const float* ln_in_g = (const float*)d_in[4];
    const float* ln_in_b = (const float*)d_in[5];
    const float* Wqkv    = (const float*)d_in[6];
    const float* bqkv    = (const float*)d_in[7];
    const float* Wo      = (const float*)d_in[8];
    const float* bo      = (const float*)d_in[9];
    const float* ln1_g   = (const float*)d_in[10];
    const float* ln1_b   = (const float*)d_in[11];
    const float* W1      = (const float*)d_in[12];
    const float* b1      = (const float*)d_in[13];
    const float* W2      = (const float*)d_in[14];
    const float* b2      = (const float*)d_in[15];
    const float* ln2_g   = (const float*)d_in[16];
    const float* ln2_b   = (const float*)d_in[17];
    const float* bn_g    = (const float*)d_in[18];
    const float* bn_b    = (const float*)d_in[19];
    float* outp = (float*)d_out;

    float *x, *y, *den, *pe;
    __nv_bfloat16 *abf, *abf2, *wtall, *qb, *kb, *vb;
    unsigned *m1, *m2;
    cudaGetSymbolAddress((void**)&x,     g_x);
    cudaGetSymbolAddress((void**)&y,     g_y);
    cudaGetSymbolAddress((void**)&den,   g_den);
    cudaGetSymbolAddress((void**)&pe,    g_pe);
    cudaGetSymbolAddress((void**)&abf,   g_abf);
    cudaGetSymbolAddress((void**)&abf2,  g_abf2);
    cudaGetSymbolAddress((void**)&wtall, g_wtall);
    cudaGetSymbolAddress((void**)&qb,    g_qb);
    cudaGetSymbolAddress((void**)&kb,    g_kb);
    cudaGetSymbolAddress((void**)&vb,    g_vb);
    cudaGetSymbolAddress((void**)&m1,    g_m1);
    cudaGetSymbolAddress((void**)&m2,    g_m2);

    cudaFuncSetAttribute(hmma_gemm_t<128>,
                         cudaFuncAttributeMaxDynamicSharedMemorySize, SMEM128);
    cudaFuncSetAttribute(hmma_gemm_t<64>,
                         cudaFuncAttributeMaxDynamicSharedMemorySize, SMEM64);

    // weight layout in g_wtall (bf16 offsets)
    const long offWin  = 0;
    const long offQKV[2] = {131072, 1179648};
    const long offWo [2] = {524288, 1572864};
    const long offW1 [2] = {655360, 1703936};
    const long offW2 [2] = {917504, 1966080};

    // 0. one-shot weight conversion
    ConvJobs J;
    J.src[0] = W_in;            J.dstOff[0] = offWin;    J.K[0] = 256; J.Nc[0] = 256;
    J.src[1] = Wqkv;            J.dstOff[1] = offQKV[0]; J.K[1] = 256; J.Nc[1] = 768;
    J.src[2] = Wo;              J.dstOff[2] = offWo[0];  J.K[2] = 256; J.Nc[2] = 256;
    J.src[3] = W1;              J.dstOff[3] = offW1[0];  J.K[3] = 256; J.Nc[3] = 512;
    J.src[4] = W2;              J.dstOff[4] = offW2[0];  J.K[4] = 512; J.Nc[4] = 256;
    J.src[5] = Wqkv + 196608;   J.dstOff[5] = offQKV[1]; J.K[5] = 256; J.Nc[5] = 768;
    J.src[6] = Wo + 65536;      J.dstOff[6] = offWo[1];  J.K[6] = 256; J.Nc[6] = 256;
    J.src[7] = W1 + 131072;     J.dstOff[7] = offW1[1];  J.K[7] = 256; J.Nc[7] = 512;
    J.src[8] = W2 + 131072;     J.dstOff[8] = offW2[1];  J.K[8] = 512; J.Nc[8] = 256;
    J.start[0] = 0;      J.start[1] = 65536;  J.start[2] = 262144;
    J.start[3] = 327680; J.start[4] = 458752; J.start[5] = 589824;
    J.start[6] = 786432; J.start[7] = 851968; J.start[8] = 983040;
    J.start[9] = 1114112;
    convW_all_kernel<<<1114112 / 256, 256>>>(J, wtall);

    // masks + PE embed
    mask_kernel<<<(BATCH * NTOK * NTOK / 32) / 8, 256>>>(dist, m1, m2);
    pe_table_kernel<<<1, 256>>>(den);
    pe_full_kernel<<<(NTOK * DIN) / 256, 256>>>(den, pe);
    add_pe_split_kernel<<<(NROWS * DIN) / 256, 256>>>(nodes, pe, abf);

    // input projection + LN(+split)
    hmma_gemm_t<64><<<dim3(2, 128), 256, SMEM64>>>(
        abf, wtall + offWin, b_in, y, nullptr, nullptr, nullptr, nullptr,
        256, 256, 0);
    ln_split_kernel<<<NROWS / 8, 256>>>(y, nullptr, ln_in_g, ln_in_b, x, abf);

    // transformer layers
    for (int l = 0; l < 2; l++) {
        hmma_gemm_t<128><<<dim3(6, 64), 256, SMEM128>>>(
            abf, wtall + offQKV[l], bqkv + l * 768, nullptr, nullptr,
            qb, kb, vb, 256, 768, 2);

        attn_mma_kernel<<<dim3(NTOK / QTA, BATCH * NHEAD), 256>>>(
            qb, kb, vb, m1, m2, abf);

        hmma_gemm_t<64><<<dim3(2, 128), 256, SMEM64>>>(
            abf, wtall + offWo[l], bo + l * 256, y, nullptr,
            nullptr, nullptr, nullptr, 256, 256, 0);
        ln_split_kernel<<<NROWS / 8, 256>>>(y, x, ln1_g + l * 256,
                                            ln1_b + l * 256, x, abf);

        hmma_gemm_t<128><<<dim3(4, 64), 256, SMEM128>>>(
            abf, wtall + offW1[l], b1 + l * 512, nullptr, abf2,
            nullptr, nullptr, nullptr, 256, 512, 1);
        hmma_gemm_t<64><<<dim3(2, 128), 256, SMEM64>>>(
            abf2, wtall + offW2[l], b2 + l * 256, y, nullptr,
            nullptr, nullptr, nullptr, 512, 256, 0);
        ln_split_kernel<<<NROWS / 8, 256>>>(y, x, ln2_g + l * 256,
                                            ln2_b + l * 256, x, abf);
    }

    // final batch-norm of x[0]
    bn_final_kernel<<<1, 256>>>(x, bn_g, bn_b, outp);
}